// round 9
// baseline (speedup 1.0000x reference)
#include <cuda_runtime.h>
#include <cuda_bf16.h>
#include <math.h>

// ---------------- problem constants ----------------
#define Bv    32
#define Himg  56
#define Wimg  56
#define Cdim  256
#define WS    7
#define NHh   8
#define HDd   32
#define KCH   16
#define KSPT  28
#define Ntok  49
#define NWb   64              // windows per image (8*8)
#define BW    (Bv*NWb)        // 2048
#define BNh   (BW*NHh)        // 16384
#define Mrows (BW*Ntok)       // 100352
#define MLPH  1024
#define QK_SCALE 0.17677669529663687f

// ---------------- scratch (device globals; no allocs allowed) ----------------
__device__ float          g_xw [Mrows*Cdim];          // fp32: feeds exact Q GEMM
__device__ float          g_q  [Mrows*Cdim];          // fp32: feeds top-k
__device__ __nv_bfloat16  g_qc [Mrows*(Cdim/2)];
__device__ float          g_k  [Mrows*(Cdim/2)];
__device__ __nv_bfloat16  g_vin[BW*KSPT*Cdim];
__device__ float          g_vp [BW*KSPT*Cdim];
__device__ __nv_bfloat16  g_o  [Mrows*Cdim];
__device__ float          g_xr [Mrows*Cdim];          // fp32 residual
__device__ __nv_bfloat16  g_x2 [Mrows*Cdim];
__device__ __nv_bfloat16  g_hb [Mrows*MLPH];
__device__ int   g_cidx[BNh*KCH];
__device__ int   g_sidx[BNh*KSPT];
// transposed bf16 weights [N][K]
__device__ __nv_bfloat16  g_wkb[(Cdim/2)*(Cdim/2)];
__device__ __nv_bfloat16  g_wvb[Cdim*Cdim];
__device__ __nv_bfloat16  g_wpb[Cdim*Cdim];
__device__ __nv_bfloat16  g_w1b[Cdim*MLPH];
__device__ __nv_bfloat16  g_w2b[MLPH*Cdim];

__device__ __forceinline__ float gelu_f(float v) {
    return 0.5f * v * (1.0f + erff(v * 0.7071067811865476f));
}

__device__ __forceinline__ unsigned f2tf(float f) {
    unsigned u;
    asm("cvt.rna.tf32.f32 %0, %1;" : "=r"(u) : "f"(f));
    return u;
}

__device__ __forceinline__ void mma8(float* d, const unsigned* a, const unsigned* b) {
    asm volatile("mma.sync.aligned.m16n8k8.row.col.f32.tf32.tf32.f32 "
        "{%0,%1,%2,%3}, {%4,%5,%6,%7}, {%8,%9}, {%0,%1,%2,%3};"
        : "+f"(d[0]), "+f"(d[1]), "+f"(d[2]), "+f"(d[3])
        : "r"(a[0]), "r"(a[1]), "r"(a[2]), "r"(a[3]), "r"(b[0]), "r"(b[1]));
}

__device__ __forceinline__ void mma16(float* d, const unsigned* a, const unsigned* b) {
    asm volatile("mma.sync.aligned.m16n8k16.row.col.f32.bf16.bf16.f32 "
        "{%0,%1,%2,%3}, {%4,%5,%6,%7}, {%8,%9}, {%0,%1,%2,%3};"
        : "+f"(d[0]), "+f"(d[1]), "+f"(d[2]), "+f"(d[3])
        : "r"(a[0]), "r"(a[1]), "r"(a[2]), "r"(a[3]), "r"(b[0]), "r"(b[1]));
}

// ---------------- weight transpose + bf16 convert: in [K][N] -> out [N][K] ----
__global__ void convw_kernel(const float* __restrict__ in, __nv_bfloat16* __restrict__ out,
                             int K, int N)
{
    int i = blockIdx.x * 256 + threadIdx.x;
    if (i >= K*N) return;
    int k = i / N, n = i % N;
    out[n*K + k] = __float2bfloat16(in[i]);
}

// ---------------- LayerNorm (one block = one row of 256) ----------------
// MODE 0: window-partition remap, fp32 out. MODE 1: identity, bf16 out.
template<int MODE>
__global__ void ln_kernel(const float* __restrict__ x, const float* __restrict__ g,
                          const float* __restrict__ b, void* __restrict__ outp)
{
    int r = blockIdx.x;
    int tid = threadIdx.x;
    float v = x[(size_t)r*Cdim + tid];
    float s = v, sq = v*v;
    __shared__ float ws[8], wq[8];
    #pragma unroll
    for (int o = 16; o > 0; o >>= 1) {
        s  += __shfl_down_sync(0xffffffffu, s,  o);
        sq += __shfl_down_sync(0xffffffffu, sq, o);
    }
    if ((tid & 31) == 0) { ws[tid >> 5] = s; wq[tid >> 5] = sq; }
    __syncthreads();
    float ts = 0.f, tq = 0.f;
    #pragma unroll
    for (int i = 0; i < 8; i++) { ts += ws[i]; tq += wq[i]; }
    float mean = ts * (1.0f/Cdim);
    float var  = tq * (1.0f/Cdim) - mean*mean;
    float rstd = rsqrtf(var + 1e-5f);
    float y = (v - mean) * rstd * g[tid] + b[tid];

    if (MODE == 0) {
        int bimg = r / (Himg*Wimg);
        int l    = r % (Himg*Wimg);
        int hr = l / Wimg, wc = l % Wimg;
        int wh = hr / WS, iwh = hr % WS;
        int ww = wc / WS, iww = wc % WS;
        int dst = ((bimg*NWb + wh*8 + ww) * Ntok) + iwh*WS + iww;
        ((float*)outp)[(size_t)dst*Cdim + tid] = y;
    } else {
        ((__nv_bfloat16*)outp)[(size_t)r*Cdim + tid] = __float2bfloat16(y);
    }
}

// ---------------- tf32 tensor-core GEMM (Q only: 3xTF32 compensated) ---------
#define ASTRIDE 36
#define BSTRIDE 132
#define ASZ (128*ASTRIDE)
#define BSZ (32*BSTRIDE)
#define GEMM_SMEM_BYTES ((2*ASZ + 2*BSZ)*4)

__global__ void __launch_bounds__(256)
tcgemm_q(const float* __restrict__ A, const float* __restrict__ Bm,
         const float* __restrict__ bias, float* __restrict__ C,
         int M, int N, int K)
{
    extern __shared__ float smf[];
    float* As = smf;
    float* Bs = smf + 2*ASZ;

    int tid  = threadIdx.x;
    int warp = tid >> 5, lane = tid & 31;
    int g = lane >> 2, t = lane & 3;
    int wm = warp >> 2, wn = warp & 3;
    int bm = blockIdx.y * 128, bn = blockIdx.x * 128;

    int arow = tid >> 3, ac4 = (tid & 7) << 2;
    int bkk  = tid >> 5, bn4 = (tid & 31) << 2;

    float acc[4][4][4];
    #pragma unroll
    for (int mi = 0; mi < 4; mi++)
        #pragma unroll
        for (int ni = 0; ni < 4; ni++)
            #pragma unroll
            for (int r = 0; r < 4; r++) acc[mi][ni][r] = 0.f;

#define QSTAGE(K0, BUF) do {                                                     \
        unsigned sa = (unsigned)__cvta_generic_to_shared(As + (BUF)*ASZ);        \
        unsigned sb = (unsigned)__cvta_generic_to_shared(Bs + (BUF)*BSZ);        \
        _Pragma("unroll")                                                        \
        for (int i = 0; i < 4; i++) {                                            \
            int row = arow + i*32;                                               \
            unsigned dst = sa + (unsigned)(row*ASTRIDE + ac4)*4u;                \
            const float* src = A + (size_t)(bm+row)*K + (K0) + ac4;              \
            asm volatile("cp.async.cg.shared.global [%0], [%1], 16;"             \
                         :: "r"(dst), "l"(src));                                 \
        }                                                                        \
        _Pragma("unroll")                                                        \
        for (int i = 0; i < 4; i++) {                                            \
            int kk = bkk + i*8;                                                  \
            unsigned dst = sb + (unsigned)(kk*BSTRIDE + bn4)*4u;                 \
            const float* src = Bm + (size_t)((K0)+kk)*N + bn + bn4;              \
            asm volatile("cp.async.cg.shared.global [%0], [%1], 16;"             \
                         :: "r"(dst), "l"(src));                                 \
        }                                                                        \
        asm volatile("cp.async.commit_group;");                                  \
    } while (0)

#define QCOMPUTE(BUF) do {                                                       \
        const float* Ab = As + (BUF)*ASZ;                                        \
        const float* Bb = Bs + (BUF)*BSZ;                                        \
        _Pragma("unroll")                                                        \
        for (int ks = 0; ks < 4; ks++) {                                         \
            int kb = ks*8;                                                       \
            unsigned ah[4][4], al[4][4];                                         \
            _Pragma("unroll")                                                    \
            for (int mi = 0; mi < 4; mi++) {                                     \
                int mrow = wm*64 + mi*16;                                        \
                float v0 = Ab[(mrow +     g)*ASTRIDE + kb + t    ];              \
                float v1 = Ab[(mrow + 8 + g)*ASTRIDE + kb + t    ];              \
                float v2 = Ab[(mrow +     g)*ASTRIDE + kb + t + 4];              \
                float v3 = Ab[(mrow + 8 + g)*ASTRIDE + kb + t + 4];              \
                ah[mi][0] = f2tf(v0); ah[mi][1] = f2tf(v1);                      \
                ah[mi][2] = f2tf(v2); ah[mi][3] = f2tf(v3);                      \
                al[mi][0] = f2tf(v0 - __uint_as_float(ah[mi][0]));               \
                al[mi][1] = f2tf(v1 - __uint_as_float(ah[mi][1]));               \
                al[mi][2] = f2tf(v2 - __uint_as_float(ah[mi][2]));               \
                al[mi][3] = f2tf(v3 - __uint_as_float(ah[mi][3]));               \
            }                                                                    \
            unsigned bh[4][2], bl[4][2];                                         \
            _Pragma("unroll")                                                    \
            for (int ni = 0; ni < 4; ni++) {                                     \
                int nc = wn*32 + ni*8;                                           \
                float u0 = Bb[(kb + t    )*BSTRIDE + nc + g];                    \
                float u1 = Bb[(kb + t + 4)*BSTRIDE + nc + g];                    \
                bh[ni][0] = f2tf(u0); bh[ni][1] = f2tf(u1);                      \
                bl[ni][0] = f2tf(u0 - __uint_as_float(bh[ni][0]));               \
                bl[ni][1] = f2tf(u1 - __uint_as_float(bh[ni][1]));               \
            }                                                                    \
            _Pragma("unroll")                                                    \
            for (int mi = 0; mi < 4; mi++)                                       \
                _Pragma("unroll")                                                \
                for (int ni = 0; ni < 4; ni++) {                                 \
                    mma8(acc[mi][ni], al[mi], bh[ni]);                           \
                    mma8(acc[mi][ni], ah[mi], bl[ni]);                           \
                    mma8(acc[mi][ni], ah[mi], bh[ni]);                           \
                }                                                                \
        }                                                                        \
    } while (0)

    int nch = K >> 5;
    QSTAGE(0, 0);
    int buf = 0;
    for (int c = 1; c < nch; c++) {
        QSTAGE(c*32, buf^1);
        asm volatile("cp.async.wait_group 1;");
        __syncthreads();
        QCOMPUTE(buf);
        __syncthreads();
        buf ^= 1;
    }
    asm volatile("cp.async.wait_group 0;");
    __syncthreads();
    QCOMPUTE(buf);

    #pragma unroll
    for (int mi = 0; mi < 4; mi++) {
        #pragma unroll
        for (int half = 0; half < 2; half++) {
            int m = bm + wm*64 + mi*16 + half*8 + g;
            #pragma unroll
            for (int ni = 0; ni < 4; ni++) {
                int n = bn + wn*32 + ni*8 + t*2;
                C[(size_t)m*N + n]     = acc[mi][ni][half*2+0] + bias[n];
                C[(size_t)m*N + n + 1] = acc[mi][ni][half*2+1] + bias[n+1];
            }
        }
    }
#undef QSTAGE
#undef QCOMPUTE
}

// ---------------- bf16 tensor-core GEMM, block 128 x (NI*32), warp 64 x (NI*8) --
// A: [M][K] bf16 row-major. Bt: [N][K] bf16 (pre-transposed). 8 warps 2x4.
// NI=4 -> block 128x128 (for N=128); NI=8 -> block 128x256.
// EPI: 0=+bias; 1=gelu(+bias); 2=+bias+res[m]; 3=+bias+res[remap] (window reverse)
// OUTBF: 1 -> store bf16, else fp32
#define BH  40            // halves per smem row (32 data + 8 pad)
#define BHW 20            // words per smem row
#define TILEA (128*BH)

template<int EPI, int OUTBF, int NI>
__global__ void __launch_bounds__(256)
bfgemm(const __nv_bfloat16* __restrict__ A, const __nv_bfloat16* __restrict__ Bt,
       const float* __restrict__ bias, void* __restrict__ Cout,
       int M, int N, int K, const float* __restrict__ res)
{
    constexpr int NB    = NI*32;       // block N
    constexpr int TILEB = NB*BH;
    extern __shared__ __nv_bfloat16 smh[];
    __nv_bfloat16* sA = smh;                 // 2 * TILEA
    __nv_bfloat16* sB = smh + 2*TILEA;       // 2 * TILEB

    int tid  = threadIdx.x;
    int warp = tid >> 5, lane = tid & 31;
    int g = lane >> 2, t = lane & 3;
    int wm = warp >> 2, wn = warp & 3;
    int bm = blockIdx.y * 128, bn = blockIdx.x * NB;

    float acc[4][NI][4];
    #pragma unroll
    for (int mi = 0; mi < 4; mi++)
        #pragma unroll
        for (int ni = 0; ni < NI; ni++)
            #pragma unroll
            for (int r = 0; r < 4; r++) acc[mi][ni][r] = 0.f;

#define BSTAGE(K0, BUF) do {                                                     \
        unsigned sa = (unsigned)__cvta_generic_to_shared(sA + (BUF)*TILEA);      \
        unsigned sb = (unsigned)__cvta_generic_to_shared(sB + (BUF)*TILEB);      \
        _Pragma("unroll")                                                        \
        for (int i = 0; i < 2; i++) {                                            \
            int p = tid + i*256;                                                 \
            int row = p >> 2, c8 = (p & 3) << 3;                                 \
            unsigned dsta = sa + (unsigned)(row*BH + c8)*2u;                     \
            const __nv_bfloat16* srca = A + (size_t)(bm+row)*K + (K0) + c8;      \
            asm volatile("cp.async.cg.shared.global [%0], [%1], 16;"             \
                         :: "r"(dsta), "l"(srca));                               \
        }                                                                        \
        _Pragma("unroll")                                                        \
        for (int i = 0; i < NB/64; i++) {                                        \
            int p = tid + i*256;                                                 \
            int row = p >> 2, c8 = (p & 3) << 3;                                 \
            unsigned dstb = sb + (unsigned)(row*BH + c8)*2u;                     \
            const __nv_bfloat16* srcb = Bt + (size_t)(bn+row)*K + (K0) + c8;     \
            asm volatile("cp.async.cg.shared.global [%0], [%1], 16;"             \
                         :: "r"(dstb), "l"(srcb));                               \
        }                                                                        \
        asm volatile("cp.async.commit_group;");                                  \
    } while (0)

#define BCOMPUTE(BUF) do {                                                       \
        const unsigned* Ab = (const unsigned*)(sA + (BUF)*TILEA);                \
        const unsigned* Bb = (const unsigned*)(sB + (BUF)*TILEB);                \
        _Pragma("unroll")                                                        \
        for (int ks = 0; ks < 2; ks++) {                                         \
            int kw = ks*8;                                                       \
            unsigned a[4][4], b[NI][2];                                          \
            _Pragma("unroll")                                                    \
            for (int mi = 0; mi < 4; mi++) {                                     \
                int mrow = wm*64 + mi*16;                                        \
                a[mi][0] = Ab[(mrow +     g)*BHW + kw + t    ];                  \
                a[mi][1] = Ab[(mrow + 8 + g)*BHW + kw + t    ];                  \
                a[mi][2] = Ab[(mrow +     g)*BHW + kw + t + 4];                  \
                a[mi][3] = Ab[(mrow + 8 + g)*BHW + kw + t + 4];                  \
            }                                                                    \
            _Pragma("unroll")                                                    \
            for (int ni = 0; ni < NI; ni++) {                                    \
                int nc = wn*(NI*8) + ni*8;                                       \
                b[ni][0] = Bb[(nc + g)*BHW + kw + t    ];                        \
                b[ni][1] = Bb[(nc + g)*BHW + kw + t + 4];                        \
            }                                                                    \
            _Pragma("unroll")                                                    \
            for (int mi = 0; mi < 4; mi++)                                       \
                _Pragma("unroll")                                                \
                for (int ni = 0; ni < NI; ni++)                                  \
                    mma16(acc[mi][ni], a[mi], b[ni]);                            \
        }                                                                        \
    } while (0)

    int nch = K >> 5;
    BSTAGE(0, 0);
    int buf = 0;
    for (int c = 1; c < nch; c++) {
        BSTAGE(c*32, buf^1);
        asm volatile("cp.async.wait_group 1;");
        __syncthreads();
        BCOMPUTE(buf);
        __syncthreads();
        buf ^= 1;
    }
    asm volatile("cp.async.wait_group 0;");
    __syncthreads();
    BCOMPUTE(buf);

    // epilogue
    #pragma unroll
    for (int mi = 0; mi < 4; mi++) {
        #pragma unroll
        for (int half = 0; half < 2; half++) {
            int m = bm + wm*64 + mi*16 + half*8 + g;
            int outrow = m;
            if (EPI == 3) {
                int bw = m / Ntok, nt = m % Ntok;
                int bimg = bw >> 6, rem = bw & 63;
                int wh = rem >> 3, ww = rem & 7;
                int hr = wh*WS + nt/WS;
                int wc = ww*WS + nt%WS;
                outrow = bimg*(Himg*Wimg) + hr*Wimg + wc;
            }
            #pragma unroll
            for (int ni = 0; ni < NI; ni++) {
                int n = bn + wn*(NI*8) + ni*8 + t*2;
                float v0 = acc[mi][ni][half*2+0] + bias[n];
                float v1 = acc[mi][ni][half*2+1] + bias[n+1];
                if (EPI == 1) { v0 = gelu_f(v0); v1 = gelu_f(v1); }
                if (EPI == 2) { v0 += res[(size_t)m*N + n]; v1 += res[(size_t)m*N + n + 1]; }
                if (EPI == 3) { v0 += res[(size_t)outrow*N + n]; v1 += res[(size_t)outrow*N + n + 1]; }
                if (OUTBF) {
                    __nv_bfloat162 p; p.x = __float2bfloat16(v0); p.y = __float2bfloat16(v1);
                    *(__nv_bfloat162*)((__nv_bfloat16*)Cout + (size_t)outrow*N + n) = p;
                } else {
                    float* Cf = (float*)Cout;
                    Cf[(size_t)outrow*N + n]     = v0;
                    Cf[(size_t)outrow*N + n + 1] = v1;
                }
            }
        }
    }
#undef BSTAGE
#undef BCOMPUTE
}

#define SMEM_NI8 ((2*TILEA + 2*(256*BH))*2)
#define SMEM_NI4 ((2*TILEA + 2*(128*BH))*2)

// ---------------- channel + spatial top-k (one block per head-window) ----------------
__global__ void topk_kernel(const float* __restrict__ wch, const float* __restrict__ bch)
{
    int bn = blockIdx.x;
    int bw = bn >> 3, hh = bn & 7;
    int tid = threadIdx.x;  // 64 threads
    __shared__ float sh[Ntok*33];
    __shared__ float feat[2*HDd];
    __shared__ float sp[HDd];
    __shared__ float tm[Ntok];
    __shared__ int   selflag[Ntok];

    for (int e = tid; e < Ntok*HDd; e += 64) {
        int n = e >> 5, d = e & 31;
        sh[n*33 + d] = g_q[((size_t)bw*Ntok + n)*Cdim + hh*HDd + d];
    }
    __syncthreads();

    if (tid < HDd) {
        float m = 0.f, mx = -1e30f;
        #pragma unroll 7
        for (int n = 0; n < Ntok; n++) {
            float v = sh[n*33 + tid];
            m += v; mx = fmaxf(mx, v);
        }
        feat[tid] = m * (1.0f/Ntok);
        feat[HDd + tid] = mx;
    }
    __syncthreads();

    if (tid < HDd) {
        float s = bch[tid];
        #pragma unroll 8
        for (int i = 0; i < 2*HDd; i++) s += feat[i]*wch[i*HDd + tid];
        sp[tid] = gelu_f(s);
    }
    __syncthreads();

    if (tid < HDd) {
        float v = sp[tid];
        int rank = 0;
        #pragma unroll 8
        for (int i = 0; i < HDd; i++) {
            float u = sp[i];
            rank += (u > v) || (u == v && i < tid);
        }
        bool sel = rank < KCH;
        unsigned mask = __ballot_sync(0xffffffffu, sel);
        if (sel) {
            int pos = __popc(mask & ((1u << tid) - 1));
            g_cidx[bn*KCH + pos] = tid;
        }
    }

    if (tid < Ntok) {
        float m = 0.f;
        #pragma unroll 8
        for (int d = 0; d < HDd; d++) m += sh[tid*33 + d];
        tm[tid] = m;
    }
    __syncthreads();
    if (tid < Ntok) {
        float v = tm[tid];
        int rank = 0;
        for (int i = 0; i < Ntok; i++) {
            float u = tm[i];
            rank += (u > v) || (u == v && i < tid);
        }
        selflag[tid] = (rank < KSPT) ? 1 : 0;
    }
    __syncthreads();
    if (tid < Ntok && selflag[tid]) {
        int pos = 0;
        for (int i = 0; i < tid; i++) pos += selflag[i];
        g_sidx[bn*KSPT + pos] = tid;
    }
}

// ---------------- gathers (fp32 g_q -> bf16 GEMM inputs) ----------------
__global__ void gather_qcha_kernel()
{
    int i = blockIdx.x * blockDim.x + threadIdx.x;
    if (i >= Mrows*(Cdim/2)) return;
    int j  = i & 15;
    int t  = i >> 4;
    int hh = t & 7;
    int rn = t >> 3;
    int n  = rn % Ntok;
    int bw = rn / Ntok;
    int c  = g_cidx[(bw*NHh + hh)*KCH + j];
    g_qc[((size_t)bw*Ntok + n)*(Cdim/2) + hh*KCH + j] =
        __float2bfloat16(g_q[((size_t)bw*Ntok + n)*Cdim + hh*HDd + c]);
}

__global__ void gather_vin_kernel()
{
    int i = blockIdx.x * blockDim.x + threadIdx.x;
    if (i >= BW*KSPT*Cdim) return;
    int d  = i & 31;
    int u  = i >> 5;
    int hh = u & 7;
    int w  = u >> 3;
    int t  = w % KSPT;
    int bw = w / KSPT;
    int n  = g_sidx[(bw*NHh + hh)*KSPT + t];
    g_vin[((size_t)bw*KSPT + t)*Cdim + hh*HDd + d] =
        __float2bfloat16(g_q[((size_t)bw*Ntok + n)*Cdim + hh*HDd + d]);
}

// ---------------- attention core (one block per window-head) ----------------
__global__ void attn_kernel(const float* __restrict__ rpb_table)
{
    int bw = blockIdx.x >> 3;
    int hh = blockIdx.x & 7;
    int bn = blockIdx.x;
    int tid = threadIdx.x;   // 128 threads

    __shared__ float s_k[Ntok][KCH];
    __shared__ float s_q[KSPT][KCH];
    __shared__ float s_v[KSPT][HDd];
    __shared__ float s_at[Ntok][KSPT];
    __shared__ int   s_si[KSPT];

    if (tid < KSPT) s_si[tid] = g_sidx[bn*KSPT + tid];
    __syncthreads();

    for (int e = tid; e < Ntok*KCH; e += 128) {
        int n = e >> 4, j = e & 15;
        s_k[n][j] = g_k[((size_t)bw*Ntok + n)*(Cdim/2) + hh*KCH + j];
    }
    for (int e = tid; e < KSPT*KCH; e += 128) {
        int t = e >> 4, j = e & 15;
        s_q[t][j] = __bfloat162float(g_qc[((size_t)bw*Ntok + s_si[t])*(Cdim/2) + hh*KCH + j]) * QK_SCALE;
    }
    for (int e = tid; e < KSPT*HDd; e += 128) {
        int t = e >> 5, d = e & 31;
        s_v[t][d] = g_vp[((size_t)bw*KSPT + t)*Cdim + hh*HDd + d];
    }
    __syncthreads();

    for (int e = tid; e < Ntok*KSPT; e += 128) {
        int n = e / KSPT, t = e % KSPT;
        float s = 0.f;
        #pragma unroll
        for (int j = 0; j < KCH; j++) s += s_k[n][j]*s_q[t][j];
        int m = s_si[t];
        int di0 = n/WS - m/WS + (WS-1);
        int di1 = n%WS - m%WS + (WS-1);
        s += rpb_table[(di0*(2*WS-1) + di1)*NHh + hh];
        s_at[n][t] = s;
    }
    __syncthreads();

    if (tid < Ntok) {
        float mean = 0.f, mx = -1e30f;
        #pragma unroll
        for (int t = 0; t < KSPT; t++) {
            float v = s_at[tid][t];
            mean += v; mx = fmaxf(mx, v);
        }
        mean *= (1.0f/KSPT);
        float gate = 1.0f / (1.0f + expf(-mean));
        float sum = 0.f;
        #pragma unroll
        for (int t = 0; t < KSPT; t++) {
            float e = expf(s_at[tid][t] - mx);
            s_at[tid][t] = e; sum += e;
        }
        float sc = gate / sum;
        #pragma unroll
        for (int t = 0; t < KSPT; t++) s_at[tid][t] *= sc;
    }
    __syncthreads();

    for (int e = tid; e < Ntok*HDd; e += 128) {
        int n = e >> 5, d = e & 31;
        float s = 0.f;
        #pragma unroll
        for (int t = 0; t < KSPT; t++) s += s_at[n][t]*s_v[t][d];
        g_o[((size_t)bw*Ntok + n)*Cdim + hh*HDd + d] = __float2bfloat16(s);
    }
}

// ---------------- launch ----------------
extern "C" void kernel_launch(void* const* d_in, const int* in_sizes, int n_in,
                              void* d_out, int out_size)
{
    const float* x       = (const float*)d_in[0];
    const float* norm1_g = (const float*)d_in[1];
    const float* norm1_b = (const float*)d_in[2];
    const float* wq      = (const float*)d_in[3];
    const float* bq      = (const float*)d_in[4];
    const float* wk      = (const float*)d_in[5];
    const float* bk      = (const float*)d_in[6];
    const float* wv      = (const float*)d_in[7];
    const float* bv      = (const float*)d_in[8];
    const float* wproj   = (const float*)d_in[9];
    const float* bproj   = (const float*)d_in[10];
    const float* wch     = (const float*)d_in[11];
    const float* bch     = (const float*)d_in[12];
    const float* rpb     = (const float*)d_in[13];
    const float* norm2_g = (const float*)d_in[14];
    const float* norm2_b = (const float*)d_in[15];
    const float* w1      = (const float*)d_in[16];
    const float* b1      = (const float*)d_in[17];
    const float* w2      = (const float*)d_in[18];
    const float* b2      = (const float*)d_in[19];
    float* out = (float*)d_out;

    float *xw, *q, *kk, *vp, *xr;
    __nv_bfloat16 *qc, *vin, *oo, *x2, *hb, *wkb, *wvb, *wpb, *w1b, *w2b;
    cudaGetSymbolAddress((void**)&xw, g_xw);
    cudaGetSymbolAddress((void**)&q,  g_q);
    cudaGetSymbolAddress((void**)&qc, g_qc);
    cudaGetSymbolAddress((void**)&kk, g_k);
    cudaGetSymbolAddress((void**)&vin,g_vin);
    cudaGetSymbolAddress((void**)&vp, g_vp);
    cudaGetSymbolAddress((void**)&oo, g_o);
    cudaGetSymbolAddress((void**)&xr, g_xr);
    cudaGetSymbolAddress((void**)&x2, g_x2);
    cudaGetSymbolAddress((void**)&hb, g_hb);
    cudaGetSymbolAddress((void**)&wkb, g_wkb);
    cudaGetSymbolAddress((void**)&wvb, g_wvb);
    cudaGetSymbolAddress((void**)&wpb, g_wpb);
    cudaGetSymbolAddress((void**)&w1b, g_w1b);
    cudaGetSymbolAddress((void**)&w2b, g_w2b);

    static bool attr_done = false;
    if (!attr_done) {
        cudaFuncSetAttribute(tcgemm_q, cudaFuncAttributeMaxDynamicSharedMemorySize, GEMM_SMEM_BYTES);
        cudaFuncSetAttribute(bfgemm<0,0,4>, cudaFuncAttributeMaxDynamicSharedMemorySize, SMEM_NI4);
        cudaFuncSetAttribute(bfgemm<0,0,8>, cudaFuncAttributeMaxDynamicSharedMemorySize, SMEM_NI8);
        cudaFuncSetAttribute(bfgemm<3,0,8>, cudaFuncAttributeMaxDynamicSharedMemorySize, SMEM_NI8);
        cudaFuncSetAttribute(bfgemm<1,1,8>, cudaFuncAttributeMaxDynamicSharedMemorySize, SMEM_NI8);
        cudaFuncSetAttribute(bfgemm<2,0,8>, cudaFuncAttributeMaxDynamicSharedMemorySize, SMEM_NI8);
        attr_done = true;
    }

    // 0. weight transposes -> bf16 [N][K]
    convw_kernel<<<((Cdim/2)*(Cdim/2)+255)/256, 256>>>(wk, wkb, Cdim/2, Cdim/2);
    convw_kernel<<<(Cdim*Cdim+255)/256, 256>>>(wv, wvb, Cdim, Cdim);
    convw_kernel<<<(Cdim*Cdim+255)/256, 256>>>(wproj, wpb, Cdim, Cdim);
    convw_kernel<<<(Cdim*MLPH+255)/256, 256>>>(w1, w1b, Cdim, MLPH);
    convw_kernel<<<(MLPH*Cdim+255)/256, 256>>>(w2, w2b, MLPH, Cdim);

    // 1. LN1 + window partition (fp32 out for Q)
    ln_kernel<0><<<Mrows, 256>>>(x, norm1_g, norm1_b, xw);

    // 2. Q = xw @ wq + bq  (3xTF32 — near-fp32, feeds top-k rankings)
    tcgemm_q<<<dim3(Cdim/128, Mrows/128), 256, GEMM_SMEM_BYTES>>>(xw, wq, bq, q, Mrows, Cdim, Cdim);

    // 3. channel + spatial top-k
    topk_kernel<<<BNh, 64>>>(wch, bch);

    // 4/5. gathers (bf16 out)
    gather_qcha_kernel<<<(Mrows*(Cdim/2)+255)/256, 256>>>();
    gather_vin_kernel<<<(BW*KSPT*Cdim+255)/256, 256>>>();

    // 6. K = qcha1 @ wk + bk   (bf16 TC, 128-wide N)
    bfgemm<0,0,4><<<dim3(1, Mrows/128), 256, SMEM_NI4>>>(qc, wkb, bk, kk, Mrows, Cdim/2, Cdim/2, nullptr);

    // 7. V = vin @ wv + bv   (256-wide N)
    bfgemm<0,0,8><<<dim3(1, (BW*KSPT)/128), 256, SMEM_NI8>>>(vin, wvb, bv, vp, BW*KSPT, Cdim, Cdim, nullptr);

    // 8. attention (bf16 out)
    attn_kernel<<<BNh, 128>>>(rpb);

    // 9. out-proj + window reverse + shortcut  -> xr (fp32)
    bfgemm<3,0,8><<<dim3(1, Mrows/128), 256, SMEM_NI8>>>(oo, wpb, bproj, xr, Mrows, Cdim, Cdim, x);

    // 10. LN2 (bf16 out)
    ln_kernel<1><<<Mrows, 256>>>(xr, norm2_g, norm2_b, x2);

    // 11. h = gelu(x2 @ w1 + b1)  (bf16 out)
    bfgemm<1,1,8><<<dim3(MLPH/256, Mrows/128), 256, SMEM_NI8>>>(x2, w1b, b1, hb, Mrows, MLPH, Cdim, nullptr);

    // 12. out = xr + h @ w2 + b2  (fp32)
    bfgemm<2,0,8><<<dim3(1, Mrows/128), 256, SMEM_NI8>>>(hb, w2b, b2, out, Mrows, Cdim, MLPH, xr);
}

// round 10
// speedup vs baseline: 1.0368x; 1.0368x over previous
#include <cuda_runtime.h>
#include <cuda_bf16.h>
#include <math.h>

// ---------------- problem constants ----------------
#define Bv    32
#define Himg  56
#define Wimg  56
#define Cdim  256
#define WS    7
#define NHh   8
#define HDd   32
#define KCH   16
#define KSPT  28
#define Ntok  49
#define NWb   64              // windows per image (8*8)
#define BW    (Bv*NWb)        // 2048
#define BNh   (BW*NHh)        // 16384
#define Mrows (BW*Ntok)       // 100352
#define MLPH  1024
#define QK_SCALE 0.17677669529663687f

// ---------------- scratch (device globals; no allocs allowed) ----------------
__device__ float          g_xw [Mrows*Cdim];          // fp32: feeds exact Q GEMM
__device__ float          g_q  [Mrows*Cdim];          // fp32: feeds top-k
__device__ __nv_bfloat16  g_qc [Mrows*(Cdim/2)];
__device__ float          g_k  [Mrows*(Cdim/2)];
__device__ __nv_bfloat16  g_vin[BW*KSPT*Cdim];
__device__ float          g_vp [BW*KSPT*Cdim];
__device__ __nv_bfloat16  g_o  [Mrows*Cdim];
__device__ float          g_xr [Mrows*Cdim];          // fp32 residual
__device__ __nv_bfloat16  g_x2 [Mrows*Cdim];
__device__ __nv_bfloat16  g_hb [Mrows*MLPH];
__device__ int   g_cidx[BNh*KCH];
__device__ int   g_sidx[BNh*KSPT];
// transposed bf16 weights [N][K]
__device__ __nv_bfloat16  g_wkb[(Cdim/2)*(Cdim/2)];
__device__ __nv_bfloat16  g_wvb[Cdim*Cdim];
__device__ __nv_bfloat16  g_wpb[Cdim*Cdim];
__device__ __nv_bfloat16  g_w1b[Cdim*MLPH];
__device__ __nv_bfloat16  g_w2b[MLPH*Cdim];

__device__ __forceinline__ float gelu_f(float v) {
    return 0.5f * v * (1.0f + erff(v * 0.7071067811865476f));
}

__device__ __forceinline__ unsigned f2tf(float f) {
    unsigned u;
    asm("cvt.rna.tf32.f32 %0, %1;" : "=r"(u) : "f"(f));
    return u;
}

__device__ __forceinline__ void mma8(float* d, const unsigned* a, const unsigned* b) {
    asm volatile("mma.sync.aligned.m16n8k8.row.col.f32.tf32.tf32.f32 "
        "{%0,%1,%2,%3}, {%4,%5,%6,%7}, {%8,%9}, {%0,%1,%2,%3};"
        : "+f"(d[0]), "+f"(d[1]), "+f"(d[2]), "+f"(d[3])
        : "r"(a[0]), "r"(a[1]), "r"(a[2]), "r"(a[3]), "r"(b[0]), "r"(b[1]));
}

__device__ __forceinline__ void mma16(float* d, const unsigned* a, const unsigned* b) {
    asm volatile("mma.sync.aligned.m16n8k16.row.col.f32.bf16.bf16.f32 "
        "{%0,%1,%2,%3}, {%4,%5,%6,%7}, {%8,%9}, {%0,%1,%2,%3};"
        : "+f"(d[0]), "+f"(d[1]), "+f"(d[2]), "+f"(d[3])
        : "r"(a[0]), "r"(a[1]), "r"(a[2]), "r"(a[3]), "r"(b[0]), "r"(b[1]));
}

// ---------------- fused weight transpose + bf16 convert (all 5 weights) ------
// each weight: in [K][N] fp32 -> out [N][K] bf16
#define WK_SZ  ((Cdim/2)*(Cdim/2))
#define WV_SZ  (Cdim*Cdim)
#define W1_SZ  (Cdim*MLPH)
#define CONV_TOTAL (WK_SZ + 2*WV_SZ + 2*W1_SZ)

__global__ void convw_all(const float* __restrict__ wk, const float* __restrict__ wv,
                          const float* __restrict__ wp, const float* __restrict__ w1,
                          const float* __restrict__ w2)
{
    int i = blockIdx.x * 256 + threadIdx.x;
    if (i >= CONV_TOTAL) return;
    const float* in; __nv_bfloat16* out; int K, N;
    if (i < WK_SZ) {
        in = wk; out = g_wkb; K = Cdim/2; N = Cdim/2;
    } else if ((i -= WK_SZ) < WV_SZ) {
        in = wv; out = g_wvb; K = Cdim; N = Cdim;
    } else if ((i -= WV_SZ) < WV_SZ) {
        in = wp; out = g_wpb; K = Cdim; N = Cdim;
    } else if ((i -= WV_SZ) < W1_SZ) {
        in = w1; out = g_w1b; K = Cdim; N = MLPH;
    } else {
        i -= W1_SZ;
        in = w2; out = g_w2b; K = MLPH; N = Cdim;
    }
    int k = i / N, n = i % N;
    out[n*K + k] = __float2bfloat16(in[i]);
}

// ---------------- LayerNorm (one block = one row of 256) ----------------
// MODE 0: window-partition remap, fp32 out. MODE 1: identity, bf16 out.
template<int MODE>
__global__ void ln_kernel(const float* __restrict__ x, const float* __restrict__ g,
                          const float* __restrict__ b, void* __restrict__ outp)
{
    int r = blockIdx.x;
    int tid = threadIdx.x;
    float v = x[(size_t)r*Cdim + tid];
    float s = v, sq = v*v;
    __shared__ float ws[8], wq[8];
    #pragma unroll
    for (int o = 16; o > 0; o >>= 1) {
        s  += __shfl_down_sync(0xffffffffu, s,  o);
        sq += __shfl_down_sync(0xffffffffu, sq, o);
    }
    if ((tid & 31) == 0) { ws[tid >> 5] = s; wq[tid >> 5] = sq; }
    __syncthreads();
    float ts = 0.f, tq = 0.f;
    #pragma unroll
    for (int i = 0; i < 8; i++) { ts += ws[i]; tq += wq[i]; }
    float mean = ts * (1.0f/Cdim);
    float var  = tq * (1.0f/Cdim) - mean*mean;
    float rstd = rsqrtf(var + 1e-5f);
    float y = (v - mean) * rstd * g[tid] + b[tid];

    if (MODE == 0) {
        int bimg = r / (Himg*Wimg);
        int l    = r % (Himg*Wimg);
        int hr = l / Wimg, wc = l % Wimg;
        int wh = hr / WS, iwh = hr % WS;
        int ww = wc / WS, iww = wc % WS;
        int dst = ((bimg*NWb + wh*8 + ww) * Ntok) + iwh*WS + iww;
        ((float*)outp)[(size_t)dst*Cdim + tid] = y;
    } else {
        ((__nv_bfloat16*)outp)[(size_t)r*Cdim + tid] = __float2bfloat16(y);
    }
}

// ---------------- tf32 tensor-core GEMM (Q only: 3xTF32 compensated) ---------
#define ASTRIDE 36
#define BSTRIDE 132
#define ASZ (128*ASTRIDE)
#define BSZ (32*BSTRIDE)
#define GEMM_SMEM_BYTES ((2*ASZ + 2*BSZ)*4)

__global__ void __launch_bounds__(256)
tcgemm_q(const float* __restrict__ A, const float* __restrict__ Bm,
         const float* __restrict__ bias, float* __restrict__ C,
         int M, int N, int K)
{
    extern __shared__ float smf[];
    float* As = smf;
    float* Bs = smf + 2*ASZ;

    int tid  = threadIdx.x;
    int warp = tid >> 5, lane = tid & 31;
    int g = lane >> 2, t = lane & 3;
    int wm = warp >> 2, wn = warp & 3;
    int bm = blockIdx.y * 128, bn = blockIdx.x * 128;

    int arow = tid >> 3, ac4 = (tid & 7) << 2;
    int bkk  = tid >> 5, bn4 = (tid & 31) << 2;

    float acc[4][4][4];
    #pragma unroll
    for (int mi = 0; mi < 4; mi++)
        #pragma unroll
        for (int ni = 0; ni < 4; ni++)
            #pragma unroll
            for (int r = 0; r < 4; r++) acc[mi][ni][r] = 0.f;

#define QSTAGE(K0, BUF) do {                                                     \
        unsigned sa = (unsigned)__cvta_generic_to_shared(As + (BUF)*ASZ);        \
        unsigned sb = (unsigned)__cvta_generic_to_shared(Bs + (BUF)*BSZ);        \
        _Pragma("unroll")                                                        \
        for (int i = 0; i < 4; i++) {                                            \
            int row = arow + i*32;                                               \
            unsigned dst = sa + (unsigned)(row*ASTRIDE + ac4)*4u;                \
            const float* src = A + (size_t)(bm+row)*K + (K0) + ac4;              \
            asm volatile("cp.async.cg.shared.global [%0], [%1], 16;"             \
                         :: "r"(dst), "l"(src));                                 \
        }                                                                        \
        _Pragma("unroll")                                                        \
        for (int i = 0; i < 4; i++) {                                            \
            int kk = bkk + i*8;                                                  \
            unsigned dst = sb + (unsigned)(kk*BSTRIDE + bn4)*4u;                 \
            const float* src = Bm + (size_t)((K0)+kk)*N + bn + bn4;              \
            asm volatile("cp.async.cg.shared.global [%0], [%1], 16;"             \
                         :: "r"(dst), "l"(src));                                 \
        }                                                                        \
        asm volatile("cp.async.commit_group;");                                  \
    } while (0)

#define QCOMPUTE(BUF) do {                                                       \
        const float* Ab = As + (BUF)*ASZ;                                        \
        const float* Bb = Bs + (BUF)*BSZ;                                        \
        _Pragma("unroll")                                                        \
        for (int ks = 0; ks < 4; ks++) {                                         \
            int kb = ks*8;                                                       \
            unsigned ah[4][4], al[4][4];                                         \
            _Pragma("unroll")                                                    \
            for (int mi = 0; mi < 4; mi++) {                                     \
                int mrow = wm*64 + mi*16;                                        \
                float v0 = Ab[(mrow +     g)*ASTRIDE + kb + t    ];              \
                float v1 = Ab[(mrow + 8 + g)*ASTRIDE + kb + t    ];              \
                float v2 = Ab[(mrow +     g)*ASTRIDE + kb + t + 4];              \
                float v3 = Ab[(mrow + 8 + g)*ASTRIDE + kb + t + 4];              \
                ah[mi][0] = f2tf(v0); ah[mi][1] = f2tf(v1);                      \
                ah[mi][2] = f2tf(v2); ah[mi][3] = f2tf(v3);                      \
                al[mi][0] = f2tf(v0 - __uint_as_float(ah[mi][0]));               \
                al[mi][1] = f2tf(v1 - __uint_as_float(ah[mi][1]));               \
                al[mi][2] = f2tf(v2 - __uint_as_float(ah[mi][2]));               \
                al[mi][3] = f2tf(v3 - __uint_as_float(ah[mi][3]));               \
            }                                                                    \
            unsigned bh[4][2], bl[4][2];                                         \
            _Pragma("unroll")                                                    \
            for (int ni = 0; ni < 4; ni++) {                                     \
                int nc = wn*32 + ni*8;                                           \
                float u0 = Bb[(kb + t    )*BSTRIDE + nc + g];                    \
                float u1 = Bb[(kb + t + 4)*BSTRIDE + nc + g];                    \
                bh[ni][0] = f2tf(u0); bh[ni][1] = f2tf(u1);                      \
                bl[ni][0] = f2tf(u0 - __uint_as_float(bh[ni][0]));               \
                bl[ni][1] = f2tf(u1 - __uint_as_float(bh[ni][1]));               \
            }                                                                    \
            _Pragma("unroll")                                                    \
            for (int mi = 0; mi < 4; mi++)                                       \
                _Pragma("unroll")                                                \
                for (int ni = 0; ni < 4; ni++) {                                 \
                    mma8(acc[mi][ni], al[mi], bh[ni]);                           \
                    mma8(acc[mi][ni], ah[mi], bl[ni]);                           \
                    mma8(acc[mi][ni], ah[mi], bh[ni]);                           \
                }                                                                \
        }                                                                        \
    } while (0)

    int nch = K >> 5;
    QSTAGE(0, 0);
    int buf = 0;
    for (int c = 1; c < nch; c++) {
        QSTAGE(c*32, buf^1);
        asm volatile("cp.async.wait_group 1;");
        __syncthreads();
        QCOMPUTE(buf);
        __syncthreads();
        buf ^= 1;
    }
    asm volatile("cp.async.wait_group 0;");
    __syncthreads();
    QCOMPUTE(buf);

    #pragma unroll
    for (int mi = 0; mi < 4; mi++) {
        #pragma unroll
        for (int half = 0; half < 2; half++) {
            int m = bm + wm*64 + mi*16 + half*8 + g;
            #pragma unroll
            for (int ni = 0; ni < 4; ni++) {
                int n = bn + wn*32 + ni*8 + t*2;
                C[(size_t)m*N + n]     = acc[mi][ni][half*2+0] + bias[n];
                C[(size_t)m*N + n + 1] = acc[mi][ni][half*2+1] + bias[n+1];
            }
        }
    }
#undef QSTAGE
#undef QCOMPUTE
}

// ---------------- bf16 tensor-core GEMM 128x128x32, 3-stage cp.async pipeline -
// A: [M][K] bf16 row-major. Bt: [N][K] bf16 (pre-transposed). 8 warps 2x4, warp 64x32.
// EPI: 0=+bias; 1=gelu(+bias); 2=+bias+res[m]; 3=+bias+res[remap] (window reverse)
// OUTBF: 1 -> store bf16, else fp32
#define BH  40            // halves per smem row (32 data + 8 pad)
#define BHW 20            // words per smem row
#define TILEH (128*BH)
#define NSTG 3
#define BF_SMEM_BYTES (NSTG*2*TILEH*2)

template<int EPI, int OUTBF>
__global__ void __launch_bounds__(256)
bfgemm(const __nv_bfloat16* __restrict__ A, const __nv_bfloat16* __restrict__ Bt,
       const float* __restrict__ bias, void* __restrict__ Cout,
       int M, int N, int K, const float* __restrict__ res)
{
    extern __shared__ __nv_bfloat16 smh[];
    __nv_bfloat16* sA = smh;                 // NSTG * TILEH
    __nv_bfloat16* sB = smh + NSTG*TILEH;    // NSTG * TILEH

    int tid  = threadIdx.x;
    int warp = tid >> 5, lane = tid & 31;
    int g = lane >> 2, t = lane & 3;
    int wm = warp >> 2, wn = warp & 3;
    int bm = blockIdx.y * 128, bn = blockIdx.x * 128;

    float acc[4][4][4];
    #pragma unroll
    for (int mi = 0; mi < 4; mi++)
        #pragma unroll
        for (int ni = 0; ni < 4; ni++)
            #pragma unroll
            for (int r = 0; r < 4; r++) acc[mi][ni][r] = 0.f;

#define BSTAGE(K0, BUF) do {                                                     \
        unsigned sa = (unsigned)__cvta_generic_to_shared(sA + (BUF)*TILEH);      \
        unsigned sb = (unsigned)__cvta_generic_to_shared(sB + (BUF)*TILEH);      \
        _Pragma("unroll")                                                        \
        for (int i = 0; i < 2; i++) {                                            \
            int p = tid + i*256;                                                 \
            int row = p >> 2, c8 = (p & 3) << 3;                                 \
            unsigned dsta = sa + (unsigned)(row*BH + c8)*2u;                     \
            const __nv_bfloat16* srca = A + (size_t)(bm+row)*K + (K0) + c8;      \
            asm volatile("cp.async.cg.shared.global [%0], [%1], 16;"             \
                         :: "r"(dsta), "l"(srca));                               \
            unsigned dstb = sb + (unsigned)(row*BH + c8)*2u;                     \
            const __nv_bfloat16* srcb = Bt + (size_t)(bn+row)*K + (K0) + c8;     \
            asm volatile("cp.async.cg.shared.global [%0], [%1], 16;"             \
                         :: "r"(dstb), "l"(srcb));                               \
        }                                                                        \
        asm volatile("cp.async.commit_group;");                                  \
    } while (0)

#define BCOMPUTE(BUF) do {                                                       \
        const unsigned* Ab = (const unsigned*)(sA + (BUF)*TILEH);                \
        const unsigned* Bb = (const unsigned*)(sB + (BUF)*TILEH);                \
        _Pragma("unroll")                                                        \
        for (int ks = 0; ks < 2; ks++) {                                         \
            int kw = ks*8;                                                       \
            unsigned a[4][4], b[4][2];                                           \
            _Pragma("unroll")                                                    \
            for (int mi = 0; mi < 4; mi++) {                                     \
                int mrow = wm*64 + mi*16;                                        \
                a[mi][0] = Ab[(mrow +     g)*BHW + kw + t    ];                  \
                a[mi][1] = Ab[(mrow + 8 + g)*BHW + kw + t    ];                  \
                a[mi][2] = Ab[(mrow +     g)*BHW + kw + t + 4];                  \
                a[mi][3] = Ab[(mrow + 8 + g)*BHW + kw + t + 4];                  \
            }                                                                    \
            _Pragma("unroll")                                                    \
            for (int ni = 0; ni < 4; ni++) {                                     \
                int nc = wn*32 + ni*8;                                           \
                b[ni][0] = Bb[(nc + g)*BHW + kw + t    ];                        \
                b[ni][1] = Bb[(nc + g)*BHW + kw + t + 4];                        \
            }                                                                    \
            _Pragma("unroll")                                                    \
            for (int mi = 0; mi < 4; mi++)                                       \
                _Pragma("unroll")                                                \
                for (int ni = 0; ni < 4; ni++)                                   \
                    mma16(acc[mi][ni], a[mi], b[ni]);                            \
        }                                                                        \
    } while (0)

    int nch = K >> 5;
    // prologue: fill first two stages
    BSTAGE(0, 0);
    if (nch > 1) BSTAGE(32, 1);
    for (int c = 0; c < nch; c++) {
        int cb = c % NSTG;
        if (c + 2 < nch) {
            BSTAGE((c+2)*32, (c+2) % NSTG);
            asm volatile("cp.async.wait_group 2;");
        } else if (c + 1 < nch) {
            asm volatile("cp.async.wait_group 1;");
        } else {
            asm volatile("cp.async.wait_group 0;");
        }
        __syncthreads();
        BCOMPUTE(cb);
        __syncthreads();
    }

    // epilogue
    #pragma unroll
    for (int mi = 0; mi < 4; mi++) {
        #pragma unroll
        for (int half = 0; half < 2; half++) {
            int m = bm + wm*64 + mi*16 + half*8 + g;
            int outrow = m;
            if (EPI == 3) {
                int bw = m / Ntok, nt = m % Ntok;
                int bimg = bw >> 6, rem = bw & 63;
                int wh = rem >> 3, ww = rem & 7;
                int hr = wh*WS + nt/WS;
                int wc = ww*WS + nt%WS;
                outrow = bimg*(Himg*Wimg) + hr*Wimg + wc;
            }
            #pragma unroll
            for (int ni = 0; ni < 4; ni++) {
                int n = bn + wn*32 + ni*8 + t*2;
                float v0 = acc[mi][ni][half*2+0] + bias[n];
                float v1 = acc[mi][ni][half*2+1] + bias[n+1];
                if (EPI == 1) { v0 = gelu_f(v0); v1 = gelu_f(v1); }
                if (EPI == 2) { v0 += res[(size_t)m*N + n]; v1 += res[(size_t)m*N + n + 1]; }
                if (EPI == 3) { v0 += res[(size_t)outrow*N + n]; v1 += res[(size_t)outrow*N + n + 1]; }
                if (OUTBF) {
                    __nv_bfloat162 p; p.x = __float2bfloat16(v0); p.y = __float2bfloat16(v1);
                    *(__nv_bfloat162*)((__nv_bfloat16*)Cout + (size_t)outrow*N + n) = p;
                } else {
                    float* Cf = (float*)Cout;
                    Cf[(size_t)outrow*N + n]     = v0;
                    Cf[(size_t)outrow*N + n + 1] = v1;
                }
            }
        }
    }
#undef BSTAGE
#undef BCOMPUTE
}

// ---------------- channel + spatial top-k (one block per head-window) ----------------
__global__ void topk_kernel(const float* __restrict__ wch, const float* __restrict__ bch)
{
    int bn = blockIdx.x;
    int bw = bn >> 3, hh = bn & 7;
    int tid = threadIdx.x;  // 64 threads
    __shared__ float sh[Ntok*33];
    __shared__ float feat[2*HDd];
    __shared__ float sp[HDd];
    __shared__ float tm[Ntok];
    __shared__ int   selflag[Ntok];

    for (int e = tid; e < Ntok*HDd; e += 64) {
        int n = e >> 5, d = e & 31;
        sh[n*33 + d] = g_q[((size_t)bw*Ntok + n)*Cdim + hh*HDd + d];
    }
    __syncthreads();

    if (tid < HDd) {
        float m = 0.f, mx = -1e30f;
        #pragma unroll 7
        for (int n = 0; n < Ntok; n++) {
            float v = sh[n*33 + tid];
            m += v; mx = fmaxf(mx, v);
        }
        feat[tid] = m * (1.0f/Ntok);
        feat[HDd + tid] = mx;
    }
    __syncthreads();

    if (tid < HDd) {
        float s = bch[tid];
        #pragma unroll 8
        for (int i = 0; i < 2*HDd; i++) s += feat[i]*wch[i*HDd + tid];
        sp[tid] = gelu_f(s);
    }
    __syncthreads();

    if (tid < HDd) {
        float v = sp[tid];
        int rank = 0;
        #pragma unroll 8
        for (int i = 0; i < HDd; i++) {
            float u = sp[i];
            rank += (u > v) || (u == v && i < tid);
        }
        bool sel = rank < KCH;
        unsigned mask = __ballot_sync(0xffffffffu, sel);
        if (sel) {
            int pos = __popc(mask & ((1u << tid) - 1));
            g_cidx[bn*KCH + pos] = tid;
        }
    }

    if (tid < Ntok) {
        float m = 0.f;
        #pragma unroll 8
        for (int d = 0; d < HDd; d++) m += sh[tid*33 + d];
        tm[tid] = m;
    }
    __syncthreads();
    if (tid < Ntok) {
        float v = tm[tid];
        int rank = 0;
        for (int i = 0; i < Ntok; i++) {
            float u = tm[i];
            rank += (u > v) || (u == v && i < tid);
        }
        selflag[tid] = (rank < KSPT) ? 1 : 0;
    }
    __syncthreads();
    if (tid < Ntok && selflag[tid]) {
        int pos = 0;
        for (int i = 0; i < tid; i++) pos += selflag[i];
        g_sidx[bn*KSPT + pos] = tid;
    }
}

// ---------------- gathers (fp32 g_q -> bf16 GEMM inputs) ----------------
__global__ void gather_qcha_kernel()
{
    int i = blockIdx.x * blockDim.x + threadIdx.x;
    if (i >= Mrows*(Cdim/2)) return;
    int j  = i & 15;
    int t  = i >> 4;
    int hh = t & 7;
    int rn = t >> 3;
    int n  = rn % Ntok;
    int bw = rn / Ntok;
    int c  = g_cidx[(bw*NHh + hh)*KCH + j];
    g_qc[((size_t)bw*Ntok + n)*(Cdim/2) + hh*KCH + j] =
        __float2bfloat16(g_q[((size_t)bw*Ntok + n)*Cdim + hh*HDd + c]);
}

__global__ void gather_vin_kernel()
{
    int i = blockIdx.x * blockDim.x + threadIdx.x;
    if (i >= BW*KSPT*Cdim) return;
    int d  = i & 31;
    int u  = i >> 5;
    int hh = u & 7;
    int w  = u >> 3;
    int t  = w % KSPT;
    int bw = w / KSPT;
    int n  = g_sidx[(bw*NHh + hh)*KSPT + t];
    g_vin[((size_t)bw*KSPT + t)*Cdim + hh*HDd + d] =
        __float2bfloat16(g_q[((size_t)bw*Ntok + n)*Cdim + hh*HDd + d]);
}

// ---------------- attention core (one block per window-head) ----------------
__global__ void attn_kernel(const float* __restrict__ rpb_table)
{
    int bw = blockIdx.x >> 3;
    int hh = blockIdx.x & 7;
    int bn = blockIdx.x;
    int tid = threadIdx.x;   // 128 threads

    __shared__ float s_k[Ntok][KCH];
    __shared__ float s_q[KSPT][KCH];
    __shared__ float s_v[KSPT][HDd];
    __shared__ float s_at[Ntok][KSPT];
    __shared__ int   s_si[KSPT];

    if (tid < KSPT) s_si[tid] = g_sidx[bn*KSPT + tid];
    __syncthreads();

    for (int e = tid; e < Ntok*KCH; e += 128) {
        int n = e >> 4, j = e & 15;
        s_k[n][j] = g_k[((size_t)bw*Ntok + n)*(Cdim/2) + hh*KCH + j];
    }
    for (int e = tid; e < KSPT*KCH; e += 128) {
        int t = e >> 4, j = e & 15;
        s_q[t][j] = __bfloat162float(g_qc[((size_t)bw*Ntok + s_si[t])*(Cdim/2) + hh*KCH + j]) * QK_SCALE;
    }
    for (int e = tid; e < KSPT*HDd; e += 128) {
        int t = e >> 5, d = e & 31;
        s_v[t][d] = g_vp[((size_t)bw*KSPT + t)*Cdim + hh*HDd + d];
    }
    __syncthreads();

    for (int e = tid; e < Ntok*KSPT; e += 128) {
        int n = e / KSPT, t = e % KSPT;
        float s = 0.f;
        #pragma unroll
        for (int j = 0; j < KCH; j++) s += s_k[n][j]*s_q[t][j];
        int m = s_si[t];
        int di0 = n/WS - m/WS + (WS-1);
        int di1 = n%WS - m%WS + (WS-1);
        s += rpb_table[(di0*(2*WS-1) + di1)*NHh + hh];
        s_at[n][t] = s;
    }
    __syncthreads();

    if (tid < Ntok) {
        float mean = 0.f, mx = -1e30f;
        #pragma unroll
        for (int t = 0; t < KSPT; t++) {
            float v = s_at[tid][t];
            mean += v; mx = fmaxf(mx, v);
        }
        mean *= (1.0f/KSPT);
        float gate = 1.0f / (1.0f + expf(-mean));
        float sum = 0.f;
        #pragma unroll
        for (int t = 0; t < KSPT; t++) {
            float e = expf(s_at[tid][t] - mx);
            s_at[tid][t] = e; sum += e;
        }
        float sc = gate / sum;
        #pragma unroll
        for (int t = 0; t < KSPT; t++) s_at[tid][t] *= sc;
    }
    __syncthreads();

    for (int e = tid; e < Ntok*HDd; e += 128) {
        int n = e >> 5, d = e & 31;
        float s = 0.f;
        #pragma unroll
        for (int t = 0; t < KSPT; t++) s += s_at[n][t]*s_v[t][d];
        g_o[((size_t)bw*Ntok + n)*Cdim + hh*HDd + d] = __float2bfloat16(s);
    }
}

// ---------------- launch ----------------
extern "C" void kernel_launch(void* const* d_in, const int* in_sizes, int n_in,
                              void* d_out, int out_size)
{
    const float* x       = (const float*)d_in[0];
    const float* norm1_g = (const float*)d_in[1];
    const float* norm1_b = (const float*)d_in[2];
    const float* wq      = (const float*)d_in[3];
    const float* bq      = (const float*)d_in[4];
    const float* wk      = (const float*)d_in[5];
    const float* bk      = (const float*)d_in[6];
    const float* wv      = (const float*)d_in[7];
    const float* bv      = (const float*)d_in[8];
    const float* wproj   = (const float*)d_in[9];
    const float* bproj   = (const float*)d_in[10];
    const float* wch     = (const float*)d_in[11];
    const float* bch     = (const float*)d_in[12];
    const float* rpb     = (const float*)d_in[13];
    const float* norm2_g = (const float*)d_in[14];
    const float* norm2_b = (const float*)d_in[15];
    const float* w1      = (const float*)d_in[16];
    const float* b1      = (const float*)d_in[17];
    const float* w2      = (const float*)d_in[18];
    const float* b2      = (const float*)d_in[19];
    float* out = (float*)d_out;

    float *xw, *q, *kk, *vp, *xr;
    __nv_bfloat16 *qc, *vin, *oo, *x2, *hb, *wkb, *wvb, *wpb, *w1b, *w2b;
    cudaGetSymbolAddress((void**)&xw, g_xw);
    cudaGetSymbolAddress((void**)&q,  g_q);
    cudaGetSymbolAddress((void**)&qc, g_qc);
    cudaGetSymbolAddress((void**)&kk, g_k);
    cudaGetSymbolAddress((void**)&vin,g_vin);
    cudaGetSymbolAddress((void**)&vp, g_vp);
    cudaGetSymbolAddress((void**)&oo, g_o);
    cudaGetSymbolAddress((void**)&xr, g_xr);
    cudaGetSymbolAddress((void**)&x2, g_x2);
    cudaGetSymbolAddress((void**)&hb, g_hb);
    cudaGetSymbolAddress((void**)&wkb, g_wkb);
    cudaGetSymbolAddress((void**)&wvb, g_wvb);
    cudaGetSymbolAddress((void**)&wpb, g_wpb);
    cudaGetSymbolAddress((void**)&w1b, g_w1b);
    cudaGetSymbolAddress((void**)&w2b, g_w2b);

    static bool attr_done = false;
    if (!attr_done) {
        cudaFuncSetAttribute(tcgemm_q, cudaFuncAttributeMaxDynamicSharedMemorySize, GEMM_SMEM_BYTES);
        cudaFuncSetAttribute(bfgemm<0,0>, cudaFuncAttributeMaxDynamicSharedMemorySize, BF_SMEM_BYTES);
        cudaFuncSetAttribute(bfgemm<3,0>, cudaFuncAttributeMaxDynamicSharedMemorySize, BF_SMEM_BYTES);
        cudaFuncSetAttribute(bfgemm<1,1>, cudaFuncAttributeMaxDynamicSharedMemorySize, BF_SMEM_BYTES);
        cudaFuncSetAttribute(bfgemm<2,0>, cudaFuncAttributeMaxDynamicSharedMemorySize, BF_SMEM_BYTES);
        attr_done = true;
    }

    // 0. weight transposes -> bf16 [N][K] (single fused launch)
    convw_all<<<(CONV_TOTAL+255)/256, 256>>>(wk, wv, wproj, w1, w2);

    // 1. LN1 + window partition (fp32 out for Q)
    ln_kernel<0><<<Mrows, 256>>>(x, norm1_g, norm1_b, xw);

    // 2. Q = xw @ wq + bq  (3xTF32 — near-fp32, feeds top-k rankings)
    tcgemm_q<<<dim3(Cdim/128, Mrows/128), 256, GEMM_SMEM_BYTES>>>(xw, wq, bq, q, Mrows, Cdim, Cdim);

    // 3. channel + spatial top-k
    topk_kernel<<<BNh, 64>>>(wch, bch);

    // 4/5. gathers (bf16 out)
    gather_qcha_kernel<<<(Mrows*(Cdim/2)+255)/256, 256>>>();
    gather_vin_kernel<<<(BW*KSPT*Cdim+255)/256, 256>>>();

    // 6. K = qcha1 @ wk + bk   (bf16 TC)
    bfgemm<0,0><<<dim3((Cdim/2)/128, Mrows/128), 256, BF_SMEM_BYTES>>>(qc, wkb, bk, kk, Mrows, Cdim/2, Cdim/2, nullptr);

    // 7. V = vin @ wv + bv
    bfgemm<0,0><<<dim3(Cdim/128, (BW*KSPT)/128), 256, BF_SMEM_BYTES>>>(vin, wvb, bv, vp, BW*KSPT, Cdim, Cdim, nullptr);

    // 8. attention (bf16 out)
    attn_kernel<<<BNh, 128>>>(rpb);

    // 9. out-proj + window reverse + shortcut  -> xr (fp32)
    bfgemm<3,0><<<dim3(Cdim/128, Mrows/128), 256, BF_SMEM_BYTES>>>(oo, wpb, bproj, xr, Mrows, Cdim, Cdim, x);

    // 10. LN2 (bf16 out)
    ln_kernel<1><<<Mrows, 256>>>(xr, norm2_g, norm2_b, x2);

    // 11. h = gelu(x2 @ w1 + b1)  (bf16 out)
    bfgemm<1,1><<<dim3(MLPH/128, Mrows/128), 256, BF_SMEM_BYTES>>>(x2, w1b, b1, hb, Mrows, MLPH, Cdim, nullptr);

    // 12. out = xr + h @ w2 + b2  (fp32)
    bfgemm<2,0><<<dim3(Cdim/128, Mrows/128), 256, BF_SMEM_BYTES>>>(hb, w2b, b2, out, Mrows, Cdim, MLPH, xr);
}

// round 11
// speedup vs baseline: 1.0557x; 1.0183x over previous
#include <cuda_runtime.h>
#include <cuda_bf16.h>
#include <math.h>

// ---------------- problem constants ----------------
#define Bv    32
#define Himg  56
#define Wimg  56
#define Cdim  256
#define WS    7
#define NHh   8
#define HDd   32
#define KCH   16
#define KSPT  28
#define Ntok  49
#define NWb   64              // windows per image (8*8)
#define BW    (Bv*NWb)        // 2048
#define BNh   (BW*NHh)        // 16384
#define Mrows (BW*Ntok)       // 100352
#define MLPH  1024
#define QK_SCALE 0.17677669529663687f

// ---------------- scratch (device globals; no allocs allowed) ----------------
__device__ float          g_xw [Mrows*Cdim];          // fp32: feeds exact Q GEMM
__device__ float          g_q  [Mrows*Cdim];          // fp32: feeds top-k
__device__ __nv_bfloat16  g_qc [Mrows*(Cdim/2)];
__device__ float          g_k  [Mrows*(Cdim/2)];
__device__ __nv_bfloat16  g_vin[BW*KSPT*Cdim];
__device__ __nv_bfloat16  g_vp [BW*KSPT*Cdim];
__device__ __nv_bfloat16  g_o  [Mrows*Cdim];
__device__ float          g_xr [Mrows*Cdim];          // fp32 residual
__device__ __nv_bfloat16  g_x2 [Mrows*Cdim];
__device__ __nv_bfloat16  g_hb [Mrows*MLPH];
__device__ int   g_cidx[BNh*KCH];
__device__ int   g_sidx[BNh*KSPT];
// transposed bf16 weights [N][K]
__device__ __nv_bfloat16  g_wkb[(Cdim/2)*(Cdim/2)];
__device__ __nv_bfloat16  g_wvb[Cdim*Cdim];
__device__ __nv_bfloat16  g_wpb[Cdim*Cdim];
__device__ __nv_bfloat16  g_w1b[Cdim*MLPH];
__device__ __nv_bfloat16  g_w2b[MLPH*Cdim];

__device__ __forceinline__ float gelu_f(float v) {
    return 0.5f * v * (1.0f + erff(v * 0.7071067811865476f));
}

__device__ __forceinline__ unsigned f2tf(float f) {
    unsigned u;
    asm("cvt.rna.tf32.f32 %0, %1;" : "=r"(u) : "f"(f));
    return u;
}

__device__ __forceinline__ void mma8(float* d, const unsigned* a, const unsigned* b) {
    asm volatile("mma.sync.aligned.m16n8k8.row.col.f32.tf32.tf32.f32 "
        "{%0,%1,%2,%3}, {%4,%5,%6,%7}, {%8,%9}, {%0,%1,%2,%3};"
        : "+f"(d[0]), "+f"(d[1]), "+f"(d[2]), "+f"(d[3])
        : "r"(a[0]), "r"(a[1]), "r"(a[2]), "r"(a[3]), "r"(b[0]), "r"(b[1]));
}

__device__ __forceinline__ void mma16(float* d, const unsigned* a, const unsigned* b) {
    asm volatile("mma.sync.aligned.m16n8k16.row.col.f32.bf16.bf16.f32 "
        "{%0,%1,%2,%3}, {%4,%5,%6,%7}, {%8,%9}, {%0,%1,%2,%3};"
        : "+f"(d[0]), "+f"(d[1]), "+f"(d[2]), "+f"(d[3])
        : "r"(a[0]), "r"(a[1]), "r"(a[2]), "r"(a[3]), "r"(b[0]), "r"(b[1]));
}

__device__ __forceinline__ void ldmx4(unsigned* r, unsigned addr) {
    asm volatile("ldmatrix.sync.aligned.m8n8.x4.shared.b16 {%0,%1,%2,%3}, [%4];"
        : "=r"(r[0]), "=r"(r[1]), "=r"(r[2]), "=r"(r[3]) : "r"(addr));
}
__device__ __forceinline__ void ldmx2(unsigned* r, unsigned addr) {
    asm volatile("ldmatrix.sync.aligned.m8n8.x2.shared.b16 {%0,%1}, [%2];"
        : "=r"(r[0]), "=r"(r[1]) : "r"(addr));
}

// ---------------- fused weight transpose + bf16 convert (all 5 weights) ------
#define WK_SZ  ((Cdim/2)*(Cdim/2))
#define WV_SZ  (Cdim*Cdim)
#define W1_SZ  (Cdim*MLPH)
#define CONV_TOTAL (WK_SZ + 2*WV_SZ + 2*W1_SZ)

__global__ void convw_all(const float* __restrict__ wk, const float* __restrict__ wv,
                          const float* __restrict__ wp, const float* __restrict__ w1,
                          const float* __restrict__ w2)
{
    int i = blockIdx.x * 256 + threadIdx.x;
    if (i >= CONV_TOTAL) return;
    const float* in; __nv_bfloat16* out; int K, N;
    if (i < WK_SZ) {
        in = wk; out = g_wkb; K = Cdim/2; N = Cdim/2;
    } else if ((i -= WK_SZ) < WV_SZ) {
        in = wv; out = g_wvb; K = Cdim; N = Cdim;
    } else if ((i -= WV_SZ) < WV_SZ) {
        in = wp; out = g_wpb; K = Cdim; N = Cdim;
    } else if ((i -= WV_SZ) < W1_SZ) {
        in = w1; out = g_w1b; K = Cdim; N = MLPH;
    } else {
        i -= W1_SZ;
        in = w2; out = g_w2b; K = MLPH; N = Cdim;
    }
    int k = i / N, n = i % N;
    out[n*K + k] = __float2bfloat16(in[i]);
}

// ---------------- LayerNorm (one block = one row of 256) ----------------
// MODE 0: window-partition remap, fp32 out. MODE 1: identity, bf16 out.
template<int MODE>
__global__ void ln_kernel(const float* __restrict__ x, const float* __restrict__ g,
                          const float* __restrict__ b, void* __restrict__ outp)
{
    int r = blockIdx.x;
    int tid = threadIdx.x;
    float v = x[(size_t)r*Cdim + tid];
    float s = v, sq = v*v;
    __shared__ float ws[8], wq[8];
    #pragma unroll
    for (int o = 16; o > 0; o >>= 1) {
        s  += __shfl_down_sync(0xffffffffu, s,  o);
        sq += __shfl_down_sync(0xffffffffu, sq, o);
    }
    if ((tid & 31) == 0) { ws[tid >> 5] = s; wq[tid >> 5] = sq; }
    __syncthreads();
    float ts = 0.f, tq = 0.f;
    #pragma unroll
    for (int i = 0; i < 8; i++) { ts += ws[i]; tq += wq[i]; }
    float mean = ts * (1.0f/Cdim);
    float var  = tq * (1.0f/Cdim) - mean*mean;
    float rstd = rsqrtf(var + 1e-5f);
    float y = (v - mean) * rstd * g[tid] + b[tid];

    if (MODE == 0) {
        int bimg = r / (Himg*Wimg);
        int l    = r % (Himg*Wimg);
        int hr = l / Wimg, wc = l % Wimg;
        int wh = hr / WS, iwh = hr % WS;
        int ww = wc / WS, iww = wc % WS;
        int dst = ((bimg*NWb + wh*8 + ww) * Ntok) + iwh*WS + iww;
        ((float*)outp)[(size_t)dst*Cdim + tid] = y;
    } else {
        ((__nv_bfloat16*)outp)[(size_t)r*Cdim + tid] = __float2bfloat16(y);
    }
}

// ---------------- tf32 tensor-core GEMM (Q only: 3xTF32 compensated) ---------
#define ASTRIDE 36
#define BSTRIDE 132
#define ASZ (128*ASTRIDE)
#define BSZ (32*BSTRIDE)
#define GEMM_SMEM_BYTES ((2*ASZ + 2*BSZ)*4)

__global__ void __launch_bounds__(256)
tcgemm_q(const float* __restrict__ A, const float* __restrict__ Bm,
         const float* __restrict__ bias, float* __restrict__ C,
         int M, int N, int K)
{
    extern __shared__ float smf[];
    float* As = smf;
    float* Bs = smf + 2*ASZ;

    int tid  = threadIdx.x;
    int warp = tid >> 5, lane = tid & 31;
    int g = lane >> 2, t = lane & 3;
    int wm = warp >> 2, wn = warp & 3;
    int bm = blockIdx.y * 128, bn = blockIdx.x * 128;

    int arow = tid >> 3, ac4 = (tid & 7) << 2;
    int bkk  = tid >> 5, bn4 = (tid & 31) << 2;

    float acc[4][4][4];
    #pragma unroll
    for (int mi = 0; mi < 4; mi++)
        #pragma unroll
        for (int ni = 0; ni < 4; ni++)
            #pragma unroll
            for (int r = 0; r < 4; r++) acc[mi][ni][r] = 0.f;

#define QSTAGE(K0, BUF) do {                                                     \
        unsigned sa = (unsigned)__cvta_generic_to_shared(As + (BUF)*ASZ);        \
        unsigned sb = (unsigned)__cvta_generic_to_shared(Bs + (BUF)*BSZ);        \
        _Pragma("unroll")                                                        \
        for (int i = 0; i < 4; i++) {                                            \
            int row = arow + i*32;                                               \
            unsigned dst = sa + (unsigned)(row*ASTRIDE + ac4)*4u;                \
            const float* src = A + (size_t)(bm+row)*K + (K0) + ac4;              \
            asm volatile("cp.async.cg.shared.global [%0], [%1], 16;"             \
                         :: "r"(dst), "l"(src));                                 \
        }                                                                        \
        _Pragma("unroll")                                                        \
        for (int i = 0; i < 4; i++) {                                            \
            int kk = bkk + i*8;                                                  \
            unsigned dst = sb + (unsigned)(kk*BSTRIDE + bn4)*4u;                 \
            const float* src = Bm + (size_t)((K0)+kk)*N + bn + bn4;              \
            asm volatile("cp.async.cg.shared.global [%0], [%1], 16;"             \
                         :: "r"(dst), "l"(src));                                 \
        }                                                                        \
        asm volatile("cp.async.commit_group;");                                  \
    } while (0)

#define QCOMPUTE(BUF) do {                                                       \
        const float* Ab = As + (BUF)*ASZ;                                        \
        const float* Bb = Bs + (BUF)*BSZ;                                        \
        _Pragma("unroll")                                                        \
        for (int ks = 0; ks < 4; ks++) {                                         \
            int kb = ks*8;                                                       \
            unsigned ah[4][4], al[4][4];                                         \
            _Pragma("unroll")                                                    \
            for (int mi = 0; mi < 4; mi++) {                                     \
                int mrow = wm*64 + mi*16;                                        \
                float v0 = Ab[(mrow +     g)*ASTRIDE + kb + t    ];              \
                float v1 = Ab[(mrow + 8 + g)*ASTRIDE + kb + t    ];              \
                float v2 = Ab[(mrow +     g)*ASTRIDE + kb + t + 4];              \
                float v3 = Ab[(mrow + 8 + g)*ASTRIDE + kb + t + 4];              \
                ah[mi][0] = f2tf(v0); ah[mi][1] = f2tf(v1);                      \
                ah[mi][2] = f2tf(v2); ah[mi][3] = f2tf(v3);                      \
                al[mi][0] = f2tf(v0 - __uint_as_float(ah[mi][0]));               \
                al[mi][1] = f2tf(v1 - __uint_as_float(ah[mi][1]));               \
                al[mi][2] = f2tf(v2 - __uint_as_float(ah[mi][2]));               \
                al[mi][3] = f2tf(v3 - __uint_as_float(ah[mi][3]));               \
            }                                                                    \
            unsigned bh[4][2], bl[4][2];                                         \
            _Pragma("unroll")                                                    \
            for (int ni = 0; ni < 4; ni++) {                                     \
                int nc = wn*32 + ni*8;                                           \
                float u0 = Bb[(kb + t    )*BSTRIDE + nc + g];                    \
                float u1 = Bb[(kb + t + 4)*BSTRIDE + nc + g];                    \
                bh[ni][0] = f2tf(u0); bh[ni][1] = f2tf(u1);                      \
                bl[ni][0] = f2tf(u0 - __uint_as_float(bh[ni][0]));               \
                bl[ni][1] = f2tf(u1 - __uint_as_float(bh[ni][1]));               \
            }                                                                    \
            _Pragma("unroll")                                                    \
            for (int mi = 0; mi < 4; mi++)                                       \
                _Pragma("unroll")                                                \
                for (int ni = 0; ni < 4; ni++) {                                 \
                    mma8(acc[mi][ni], al[mi], bh[ni]);                           \
                    mma8(acc[mi][ni], ah[mi], bl[ni]);                           \
                    mma8(acc[mi][ni], ah[mi], bh[ni]);                           \
                }                                                                \
        }                                                                        \
    } while (0)

    int nch = K >> 5;
    QSTAGE(0, 0);
    int buf = 0;
    for (int c = 1; c < nch; c++) {
        QSTAGE(c*32, buf^1);
        asm volatile("cp.async.wait_group 1;");
        __syncthreads();
        QCOMPUTE(buf);
        __syncthreads();
        buf ^= 1;
    }
    asm volatile("cp.async.wait_group 0;");
    __syncthreads();
    QCOMPUTE(buf);

    #pragma unroll
    for (int mi = 0; mi < 4; mi++) {
        #pragma unroll
        for (int half = 0; half < 2; half++) {
            int m = bm + wm*64 + mi*16 + half*8 + g;
            #pragma unroll
            for (int ni = 0; ni < 4; ni++) {
                int n = bn + wn*32 + ni*8 + t*2;
                C[(size_t)m*N + n]     = acc[mi][ni][half*2+0] + bias[n];
                C[(size_t)m*N + n + 1] = acc[mi][ni][half*2+1] + bias[n+1];
            }
        }
    }
#undef QSTAGE
#undef QCOMPUTE
}

// ---------------- bf16 tensor-core GEMM 128x128x32, 2-stage, ldmatrix frags ---
// A: [M][K] bf16 row-major. Bt: [N][K] bf16 (pre-transposed). 8 warps 2x4, warp 64x32.
// EPI: 0=+bias; 1=gelu(+bias); 2=+bias+res[m]; 3=+bias+res[remap] (window reverse)
// OUTBF: 1 -> store bf16, else fp32
#define BH  40            // halves per smem row (32 data + 8 pad); 80B row stride
#define TILEH (128*BH)
#define BF_SMEM_BYTES (2*2*TILEH*2)

template<int EPI, int OUTBF>
__global__ void __launch_bounds__(256)
bfgemm(const __nv_bfloat16* __restrict__ A, const __nv_bfloat16* __restrict__ Bt,
       const float* __restrict__ bias, void* __restrict__ Cout,
       int M, int N, int K, const float* __restrict__ res)
{
    extern __shared__ __nv_bfloat16 smh[];
    __nv_bfloat16* sA = smh;                 // 2 * TILEH
    __nv_bfloat16* sB = smh + 2*TILEH;       // 2 * TILEH

    int tid  = threadIdx.x;
    int warp = tid >> 5, lane = tid & 31;
    int g = lane >> 2, t = lane & 3;
    int wm = warp >> 2, wn = warp & 3;
    int bm = blockIdx.y * 128, bn = blockIdx.x * 128;

    // ldmatrix per-lane addressing (halves):
    // A x4 tiles: t0=(r0-7,k0-7) t1=(r8-15,k0-7) t2=(r0-7,k8-15) t3=(r8-15,k8-15)
    int tA = lane >> 3;
    int arow_f = ((tA & 1) << 3) + (lane & 7);   // row within 16
    int akofs  = (tA >> 1) << 3;                 // k-halves offset
    // B x2 tiles: t0=(n0-7,k0-7) t1=(n0-7,k8-15); lanes 0-15 supply addrs
    int brow_f = lane & 7;
    int bkofs  = ((lane >> 3) & 1) << 3;

    float acc[4][4][4];
    #pragma unroll
    for (int mi = 0; mi < 4; mi++)
        #pragma unroll
        for (int ni = 0; ni < 4; ni++)
            #pragma unroll
            for (int r = 0; r < 4; r++) acc[mi][ni][r] = 0.f;

#define BSTAGE(K0, BUF) do {                                                     \
        unsigned sa = (unsigned)__cvta_generic_to_shared(sA + (BUF)*TILEH);      \
        unsigned sb = (unsigned)__cvta_generic_to_shared(sB + (BUF)*TILEH);      \
        _Pragma("unroll")                                                        \
        for (int i = 0; i < 2; i++) {                                            \
            int p = tid + i*256;                                                 \
            int row = p >> 2, c8 = (p & 3) << 3;                                 \
            unsigned dsta = sa + (unsigned)(row*BH + c8)*2u;                     \
            const __nv_bfloat16* srca = A + (size_t)(bm+row)*K + (K0) + c8;      \
            asm volatile("cp.async.cg.shared.global [%0], [%1], 16;"             \
                         :: "r"(dsta), "l"(srca));                               \
            unsigned dstb = sb + (unsigned)(row*BH + c8)*2u;                     \
            const __nv_bfloat16* srcb = Bt + (size_t)(bn+row)*K + (K0) + c8;     \
            asm volatile("cp.async.cg.shared.global [%0], [%1], 16;"             \
                         :: "r"(dstb), "l"(srcb));                               \
        }                                                                        \
        asm volatile("cp.async.commit_group;");                                  \
    } while (0)

#define BCOMPUTE(BUF) do {                                                       \
        unsigned sa = (unsigned)__cvta_generic_to_shared(sA + (BUF)*TILEH);      \
        unsigned sb = (unsigned)__cvta_generic_to_shared(sB + (BUF)*TILEH);      \
        _Pragma("unroll")                                                        \
        for (int ks = 0; ks < 2; ks++) {                                         \
            unsigned a[4][4], b[4][2];                                           \
            _Pragma("unroll")                                                    \
            for (int mi = 0; mi < 4; mi++) {                                     \
                unsigned ad = sa + (unsigned)((wm*64 + mi*16 + arow_f)*BH        \
                                              + ks*16 + akofs)*2u;               \
                ldmx4(a[mi], ad);                                                \
            }                                                                    \
            _Pragma("unroll")                                                    \
            for (int ni = 0; ni < 4; ni++) {                                     \
                unsigned bd = sb + (unsigned)((wn*32 + ni*8 + brow_f)*BH         \
                                              + ks*16 + bkofs)*2u;               \
                ldmx2(b[ni], bd);                                                \
            }                                                                    \
            _Pragma("unroll")                                                    \
            for (int mi = 0; mi < 4; mi++)                                       \
                _Pragma("unroll")                                                \
                for (int ni = 0; ni < 4; ni++)                                   \
                    mma16(acc[mi][ni], a[mi], b[ni]);                            \
        }                                                                        \
    } while (0)

    int nch = K >> 5;
    BSTAGE(0, 0);
    int buf = 0;
    for (int c = 1; c < nch; c++) {
        BSTAGE(c*32, buf^1);
        asm volatile("cp.async.wait_group 1;");
        __syncthreads();
        BCOMPUTE(buf);
        __syncthreads();
        buf ^= 1;
    }
    asm volatile("cp.async.wait_group 0;");
    __syncthreads();
    BCOMPUTE(buf);

    // epilogue
    #pragma unroll
    for (int mi = 0; mi < 4; mi++) {
        #pragma unroll
        for (int half = 0; half < 2; half++) {
            int m = bm + wm*64 + mi*16 + half*8 + g;
            int outrow = m;
            if (EPI == 3) {
                int bw = m / Ntok, nt = m % Ntok;
                int bimg = bw >> 6, rem = bw & 63;
                int wh = rem >> 3, ww = rem & 7;
                int hr = wh*WS + nt/WS;
                int wc = ww*WS + nt%WS;
                outrow = bimg*(Himg*Wimg) + hr*Wimg + wc;
            }
            #pragma unroll
            for (int ni = 0; ni < 4; ni++) {
                int n = bn + wn*32 + ni*8 + t*2;
                float v0 = acc[mi][ni][half*2+0] + bias[n];
                float v1 = acc[mi][ni][half*2+1] + bias[n+1];
                if (EPI == 1) { v0 = gelu_f(v0); v1 = gelu_f(v1); }
                if (EPI == 2) { v0 += res[(size_t)m*N + n]; v1 += res[(size_t)m*N + n + 1]; }
                if (EPI == 3) { v0 += res[(size_t)outrow*N + n]; v1 += res[(size_t)outrow*N + n + 1]; }
                if (OUTBF) {
                    __nv_bfloat162 p; p.x = __float2bfloat16(v0); p.y = __float2bfloat16(v1);
                    *(__nv_bfloat162*)((__nv_bfloat16*)Cout + (size_t)outrow*N + n) = p;
                } else {
                    float* Cf = (float*)Cout;
                    Cf[(size_t)outrow*N + n]     = v0;
                    Cf[(size_t)outrow*N + n + 1] = v1;
                }
            }
        }
    }
#undef BSTAGE
#undef BCOMPUTE
}

// ---------------- channel + spatial top-k (one block per head-window) ----------------
__global__ void topk_kernel(const float* __restrict__ wch, const float* __restrict__ bch)
{
    int bn = blockIdx.x;
    int bw = bn >> 3, hh = bn & 7;
    int tid = threadIdx.x;  // 64 threads
    __shared__ float sh[Ntok*33];
    __shared__ float feat[2*HDd];
    __shared__ float sp[HDd];
    __shared__ float tm[Ntok];
    __shared__ int   selflag[Ntok];

    for (int e = tid; e < Ntok*HDd; e += 64) {
        int n = e >> 5, d = e & 31;
        sh[n*33 + d] = g_q[((size_t)bw*Ntok + n)*Cdim + hh*HDd + d];
    }
    __syncthreads();

    if (tid < HDd) {
        float m = 0.f, mx = -1e30f;
        #pragma unroll 7
        for (int n = 0; n < Ntok; n++) {
            float v = sh[n*33 + tid];
            m += v; mx = fmaxf(mx, v);
        }
        feat[tid] = m * (1.0f/Ntok);
        feat[HDd + tid] = mx;
    }
    __syncthreads();

    if (tid < HDd) {
        float s = bch[tid];
        #pragma unroll 8
        for (int i = 0; i < 2*HDd; i++) s += feat[i]*wch[i*HDd + tid];
        sp[tid] = gelu_f(s);
    }
    __syncthreads();

    if (tid < HDd) {
        float v = sp[tid];
        int rank = 0;
        #pragma unroll 8
        for (int i = 0; i < HDd; i++) {
            float u = sp[i];
            rank += (u > v) || (u == v && i < tid);
        }
        bool sel = rank < KCH;
        unsigned mask = __ballot_sync(0xffffffffu, sel);
        if (sel) {
            int pos = __popc(mask & ((1u << tid) - 1));
            g_cidx[bn*KCH + pos] = tid;
        }
    }

    if (tid < Ntok) {
        float m = 0.f;
        #pragma unroll 8
        for (int d = 0; d < HDd; d++) m += sh[tid*33 + d];
        tm[tid] = m;
    }
    __syncthreads();
    if (tid < Ntok) {
        float v = tm[tid];
        int rank = 0;
        for (int i = 0; i < Ntok; i++) {
            float u = tm[i];
            rank += (u > v) || (u == v && i < tid);
        }
        selflag[tid] = (rank < KSPT) ? 1 : 0;
    }
    __syncthreads();
    if (tid < Ntok && selflag[tid]) {
        int pos = 0;
        for (int i = 0; i < tid; i++) pos += selflag[i];
        g_sidx[bn*KSPT + pos] = tid;
    }
}

// ---------------- gathers (fp32 g_q -> bf16 GEMM inputs) ----------------
__global__ void gather_qcha_kernel()
{
    int i = blockIdx.x * blockDim.x + threadIdx.x;
    if (i >= Mrows*(Cdim/2)) return;
    int j  = i & 15;
    int t  = i >> 4;
    int hh = t & 7;
    int rn = t >> 3;
    int n  = rn % Ntok;
    int bw = rn / Ntok;
    int c  = g_cidx[(bw*NHh + hh)*KCH + j];
    g_qc[((size_t)bw*Ntok + n)*(Cdim/2) + hh*KCH + j] =
        __float2bfloat16(g_q[((size_t)bw*Ntok + n)*Cdim + hh*HDd + c]);
}

__global__ void gather_vin_kernel()
{
    int i = blockIdx.x * blockDim.x + threadIdx.x;
    if (i >= BW*KSPT*Cdim) return;
    int d  = i & 31;
    int u  = i >> 5;
    int hh = u & 7;
    int w  = u >> 3;
    int t  = w % KSPT;
    int bw = w / KSPT;
    int n  = g_sidx[(bw*NHh + hh)*KSPT + t];
    g_vin[((size_t)bw*KSPT + t)*Cdim + hh*HDd + d] =
        __float2bfloat16(g_q[((size_t)bw*Ntok + n)*Cdim + hh*HDd + d]);
}

// ---------------- attention core (one block per window-head) ----------------
__global__ void attn_kernel(const float* __restrict__ rpb_table)
{
    int bw = blockIdx.x >> 3;
    int hh = blockIdx.x & 7;
    int bn = blockIdx.x;
    int tid = threadIdx.x;   // 128 threads

    __shared__ float s_k[Ntok][KCH];
    __shared__ float s_q[KSPT][KCH];
    __shared__ float s_v[KSPT][HDd];
    __shared__ float s_at[Ntok][KSPT];
    __shared__ int   s_si[KSPT];

    if (tid < KSPT) s_si[tid] = g_sidx[bn*KSPT + tid];
    __syncthreads();

    for (int e = tid; e < Ntok*KCH; e += 128) {
        int n = e >> 4, j = e & 15;
        s_k[n][j] = g_k[((size_t)bw*Ntok + n)*(Cdim/2) + hh*KCH + j];
    }
    for (int e = tid; e < KSPT*KCH; e += 128) {
        int t = e >> 4, j = e & 15;
        s_q[t][j] = __bfloat162float(g_qc[((size_t)bw*Ntok + s_si[t])*(Cdim/2) + hh*KCH + j]) * QK_SCALE;
    }
    for (int e = tid; e < KSPT*HDd; e += 128) {
        int t = e >> 5, d = e & 31;
        s_v[t][d] = __bfloat162float(g_vp[((size_t)bw*KSPT + t)*Cdim + hh*HDd + d]);
    }
    __syncthreads();

    for (int e = tid; e < Ntok*KSPT; e += 128) {
        int n = e / KSPT, t = e % KSPT;
        float s = 0.f;
        #pragma unroll
        for (int j = 0; j < KCH; j++) s += s_k[n][j]*s_q[t][j];
        int m = s_si[t];
        int di0 = n/WS - m/WS + (WS-1);
        int di1 = n%WS - m%WS + (WS-1);
        s += rpb_table[(di0*(2*WS-1) + di1)*NHh + hh];
        s_at[n][t] = s;
    }
    __syncthreads();

    if (tid < Ntok) {
        float mean = 0.f, mx = -1e30f;
        #pragma unroll
        for (int t = 0; t < KSPT; t++) {
            float v = s_at[tid][t];
            mean += v; mx = fmaxf(mx, v);
        }
        mean *= (1.0f/KSPT);
        float gate = 1.0f / (1.0f + expf(-mean));
        float sum = 0.f;
        #pragma unroll
        for (int t = 0; t < KSPT; t++) {
            float e = expf(s_at[tid][t] - mx);
            s_at[tid][t] = e; sum += e;
        }
        float sc = gate / sum;
        #pragma unroll
        for (int t = 0; t < KSPT; t++) s_at[tid][t] *= sc;
    }
    __syncthreads();

    for (int e = tid; e < Ntok*HDd; e += 128) {
        int n = e >> 5, d = e & 31;
        float s = 0.f;
        #pragma unroll
        for (int t = 0; t < KSPT; t++) s += s_at[n][t]*s_v[t][d];
        g_o[((size_t)bw*Ntok + n)*Cdim + hh*HDd + d] = __float2bfloat16(s);
    }
}

// ---------------- launch ----------------
extern "C" void kernel_launch(void* const* d_in, const int* in_sizes, int n_in,
                              void* d_out, int out_size)
{
    const float* x       = (const float*)d_in[0];
    const float* norm1_g = (const float*)d_in[1];
    const float* norm1_b = (const float*)d_in[2];
    const float* wq      = (const float*)d_in[3];
    const float* bq      = (const float*)d_in[4];
    const float* wk      = (const float*)d_in[5];
    const float* bk      = (const float*)d_in[6];
    const float* wv      = (const float*)d_in[7];
    const float* bv      = (const float*)d_in[8];
    const float* wproj   = (const float*)d_in[9];
    const float* bproj   = (const float*)d_in[10];
    const float* wch     = (const float*)d_in[11];
    const float* bch     = (const float*)d_in[12];
    const float* rpb     = (const float*)d_in[13];
    const float* norm2_g = (const float*)d_in[14];
    const float* norm2_b = (const float*)d_in[15];
    const float* w1      = (const float*)d_in[16];
    const float* b1      = (const float*)d_in[17];
    const float* w2      = (const float*)d_in[18];
    const float* b2      = (const float*)d_in[19];
    float* out = (float*)d_out;

    float *xw, *q, *kk, *xr;
    __nv_bfloat16 *qc, *vin, *vp, *oo, *x2, *hb, *wkb, *wvb, *wpb, *w1b, *w2b;
    cudaGetSymbolAddress((void**)&xw, g_xw);
    cudaGetSymbolAddress((void**)&q,  g_q);
    cudaGetSymbolAddress((void**)&qc, g_qc);
    cudaGetSymbolAddress((void**)&kk, g_k);
    cudaGetSymbolAddress((void**)&vin,g_vin);
    cudaGetSymbolAddress((void**)&vp, g_vp);
    cudaGetSymbolAddress((void**)&oo, g_o);
    cudaGetSymbolAddress((void**)&xr, g_xr);
    cudaGetSymbolAddress((void**)&x2, g_x2);
    cudaGetSymbolAddress((void**)&hb, g_hb);
    cudaGetSymbolAddress((void**)&wkb, g_wkb);
    cudaGetSymbolAddress((void**)&wvb, g_wvb);
    cudaGetSymbolAddress((void**)&wpb, g_wpb);
    cudaGetSymbolAddress((void**)&w1b, g_w1b);
    cudaGetSymbolAddress((void**)&w2b, g_w2b);

    static bool attr_done = false;
    if (!attr_done) {
        cudaFuncSetAttribute(tcgemm_q, cudaFuncAttributeMaxDynamicSharedMemorySize, GEMM_SMEM_BYTES);
        cudaFuncSetAttribute(bfgemm<0,0>, cudaFuncAttributeMaxDynamicSharedMemorySize, BF_SMEM_BYTES);
        cudaFuncSetAttribute(bfgemm<0,1>, cudaFuncAttributeMaxDynamicSharedMemorySize, BF_SMEM_BYTES);
        cudaFuncSetAttribute(bfgemm<3,0>, cudaFuncAttributeMaxDynamicSharedMemorySize, BF_SMEM_BYTES);
        cudaFuncSetAttribute(bfgemm<1,1>, cudaFuncAttributeMaxDynamicSharedMemorySize, BF_SMEM_BYTES);
        cudaFuncSetAttribute(bfgemm<2,0>, cudaFuncAttributeMaxDynamicSharedMemorySize, BF_SMEM_BYTES);
        attr_done = true;
    }

    // 0. weight transposes -> bf16 [N][K] (single fused launch)
    convw_all<<<(CONV_TOTAL+255)/256, 256>>>(wk, wv, wproj, w1, w2);

    // 1. LN1 + window partition (fp32 out for Q)
    ln_kernel<0><<<Mrows, 256>>>(x, norm1_g, norm1_b, xw);

    // 2. Q = xw @ wq + bq  (3xTF32 — near-fp32, feeds top-k rankings)
    tcgemm_q<<<dim3(Cdim/128, Mrows/128), 256, GEMM_SMEM_BYTES>>>(xw, wq, bq, q, Mrows, Cdim, Cdim);

    // 3. channel + spatial top-k
    topk_kernel<<<BNh, 64>>>(wch, bch);

    // 4/5. gathers (bf16 out)
    gather_qcha_kernel<<<(Mrows*(Cdim/2)+255)/256, 256>>>();
    gather_vin_kernel<<<(BW*KSPT*Cdim+255)/256, 256>>>();

    // 6. K = qcha1 @ wk + bk   (bf16 TC)
    bfgemm<0,0><<<dim3((Cdim/2)/128, Mrows/128), 256, BF_SMEM_BYTES>>>(qc, wkb, bk, kk, Mrows, Cdim/2, Cdim/2, nullptr);

    // 7. V = vin @ wv + bv  (bf16 out)
    bfgemm<0,1><<<dim3(Cdim/128, (BW*KSPT)/128), 256, BF_SMEM_BYTES>>>(vin, wvb, bv, vp, BW*KSPT, Cdim, Cdim, nullptr);

    // 8. attention (bf16 out)
    attn_kernel<<<BNh, 128>>>(rpb);

    // 9. out-proj + window reverse + shortcut  -> xr (fp32)
    bfgemm<3,0><<<dim3(Cdim/128, Mrows/128), 256, BF_SMEM_BYTES>>>(oo, wpb, bproj, xr, Mrows, Cdim, Cdim, x);

    // 10. LN2 (bf16 out)
    ln_kernel<1><<<Mrows, 256>>>(xr, norm2_g, norm2_b, x2);

    // 11. h = gelu(x2 @ w1 + b1)  (bf16 out)
    bfgemm<1,1><<<dim3(MLPH/128, Mrows/128), 256, BF_SMEM_BYTES>>>(x2, w1b, b1, hb, Mrows, MLPH, Cdim, nullptr);

    // 12. out = xr + h @ w2 + b2  (fp32)
    bfgemm<2,0><<<dim3(Cdim/128, Mrows/128), 256, BF_SMEM_BYTES>>>(hb, w2b, b2, out, Mrows, Cdim, MLPH, xr);
}

// round 12
// speedup vs baseline: 1.1309x; 1.0713x over previous
#include <cuda_runtime.h>
#include <cuda_bf16.h>
#include <math.h>

// ---------------- problem constants ----------------
#define Bv    32
#define Himg  56
#define Wimg  56
#define Cdim  256
#define WS    7
#define NHh   8
#define HDd   32
#define KCH   16
#define KSPT  28
#define Ntok  49
#define NWb   64              // windows per image (8*8)
#define BW    (Bv*NWb)        // 2048
#define BNh   (BW*NHh)        // 16384
#define Mrows (BW*Ntok)       // 100352
#define MLPH  1024
#define QK_SCALE 0.17677669529663687f

// ---------------- scratch (device globals; no allocs allowed) ----------------
__device__ float          g_xw [Mrows*Cdim];          // fp32: feeds exact Q GEMM
__device__ float          g_q  [Mrows*Cdim];          // fp32: feeds top-k
__device__ __nv_bfloat16  g_qc [Mrows*(Cdim/2)];
__device__ __nv_bfloat16  g_kb [Mrows*(Cdim/2)];
__device__ __nv_bfloat16  g_vin[BW*KSPT*Cdim];
__device__ __nv_bfloat16  g_vp [BW*KSPT*Cdim];
__device__ __nv_bfloat16  g_o  [Mrows*Cdim];
__device__ float          g_xr [Mrows*Cdim];          // fp32 residual
__device__ __nv_bfloat16  g_x2 [Mrows*Cdim];
__device__ __nv_bfloat16  g_hb [Mrows*MLPH];
__device__ int   g_sidx[BNh*KSPT];
// transposed bf16 weights [N][K]
__device__ __nv_bfloat16  g_wkb[(Cdim/2)*(Cdim/2)];
__device__ __nv_bfloat16  g_wvb[Cdim*Cdim];
__device__ __nv_bfloat16  g_wpb[Cdim*Cdim];
__device__ __nv_bfloat16  g_w1b[Cdim*MLPH];
__device__ __nv_bfloat16  g_w2b[MLPH*Cdim];

__device__ __forceinline__ float gelu_f(float v) {
    return 0.5f * v * (1.0f + erff(v * 0.7071067811865476f));
}

__device__ __forceinline__ unsigned f2tf(float f) {
    unsigned u;
    asm("cvt.rna.tf32.f32 %0, %1;" : "=r"(u) : "f"(f));
    return u;
}

__device__ __forceinline__ void mma8(float* d, const unsigned* a, const unsigned* b) {
    asm volatile("mma.sync.aligned.m16n8k8.row.col.f32.tf32.tf32.f32 "
        "{%0,%1,%2,%3}, {%4,%5,%6,%7}, {%8,%9}, {%0,%1,%2,%3};"
        : "+f"(d[0]), "+f"(d[1]), "+f"(d[2]), "+f"(d[3])
        : "r"(a[0]), "r"(a[1]), "r"(a[2]), "r"(a[3]), "r"(b[0]), "r"(b[1]));
}

__device__ __forceinline__ void mma16(float* d, const unsigned* a, const unsigned* b) {
    asm volatile("mma.sync.aligned.m16n8k16.row.col.f32.bf16.bf16.f32 "
        "{%0,%1,%2,%3}, {%4,%5,%6,%7}, {%8,%9}, {%0,%1,%2,%3};"
        : "+f"(d[0]), "+f"(d[1]), "+f"(d[2]), "+f"(d[3])
        : "r"(a[0]), "r"(a[1]), "r"(a[2]), "r"(a[3]), "r"(b[0]), "r"(b[1]));
}

__device__ __forceinline__ void ldmx4(unsigned* r, unsigned addr) {
    asm volatile("ldmatrix.sync.aligned.m8n8.x4.shared.b16 {%0,%1,%2,%3}, [%4];"
        : "=r"(r[0]), "=r"(r[1]), "=r"(r[2]), "=r"(r[3]) : "r"(addr));
}
__device__ __forceinline__ void ldmx2(unsigned* r, unsigned addr) {
    asm volatile("ldmatrix.sync.aligned.m8n8.x2.shared.b16 {%0,%1}, [%2];"
        : "=r"(r[0]), "=r"(r[1]) : "r"(addr));
}

// ---------------- fused weight transpose + bf16 convert (all 5 weights) ------
#define WK_SZ  ((Cdim/2)*(Cdim/2))
#define WV_SZ  (Cdim*Cdim)
#define W1_SZ  (Cdim*MLPH)
#define CONV_TOTAL (WK_SZ + 2*WV_SZ + 2*W1_SZ)

__global__ void convw_all(const float* __restrict__ wk, const float* __restrict__ wv,
                          const float* __restrict__ wp, const float* __restrict__ w1,
                          const float* __restrict__ w2)
{
    int i = blockIdx.x * 256 + threadIdx.x;
    if (i >= CONV_TOTAL) return;
    const float* in; __nv_bfloat16* out; int K, N;
    if (i < WK_SZ) {
        in = wk; out = g_wkb; K = Cdim/2; N = Cdim/2;
    } else if ((i -= WK_SZ) < WV_SZ) {
        in = wv; out = g_wvb; K = Cdim; N = Cdim;
    } else if ((i -= WV_SZ) < WV_SZ) {
        in = wp; out = g_wpb; K = Cdim; N = Cdim;
    } else if ((i -= WV_SZ) < W1_SZ) {
        in = w1; out = g_w1b; K = Cdim; N = MLPH;
    } else {
        i -= W1_SZ;
        in = w2; out = g_w2b; K = MLPH; N = Cdim;
    }
    int k = i / N, n = i % N;
    out[n*K + k] = __float2bfloat16(in[i]);
}

// ---------------- LayerNorm (one block = one row of 256) ----------------
// MODE 0: window-partition remap, fp32 out. MODE 1: identity, bf16 out.
template<int MODE>
__global__ void ln_kernel(const float* __restrict__ x, const float* __restrict__ g,
                          const float* __restrict__ b, void* __restrict__ outp)
{
    int r = blockIdx.x;
    int tid = threadIdx.x;
    float v = x[(size_t)r*Cdim + tid];
    float s = v, sq = v*v;
    __shared__ float ws[8], wq[8];
    #pragma unroll
    for (int o = 16; o > 0; o >>= 1) {
        s  += __shfl_down_sync(0xffffffffu, s,  o);
        sq += __shfl_down_sync(0xffffffffu, sq, o);
    }
    if ((tid & 31) == 0) { ws[tid >> 5] = s; wq[tid >> 5] = sq; }
    __syncthreads();
    float ts = 0.f, tq = 0.f;
    #pragma unroll
    for (int i = 0; i < 8; i++) { ts += ws[i]; tq += wq[i]; }
    float mean = ts * (1.0f/Cdim);
    float var  = tq * (1.0f/Cdim) - mean*mean;
    float rstd = rsqrtf(var + 1e-5f);
    float y = (v - mean) * rstd * g[tid] + b[tid];

    if (MODE == 0) {
        int bimg = r / (Himg*Wimg);
        int l    = r % (Himg*Wimg);
        int hr = l / Wimg, wc = l % Wimg;
        int wh = hr / WS, iwh = hr % WS;
        int ww = wc / WS, iww = wc % WS;
        int dst = ((bimg*NWb + wh*8 + ww) * Ntok) + iwh*WS + iww;
        ((float*)outp)[(size_t)dst*Cdim + tid] = y;
    } else {
        ((__nv_bfloat16*)outp)[(size_t)r*Cdim + tid] = __float2bfloat16(y);
    }
}

// ---------------- tf32 tensor-core GEMM (Q only: 3xTF32 compensated) ---------
#define ASTRIDE 36
#define BSTRIDE 132
#define ASZ (128*ASTRIDE)
#define BSZ (32*BSTRIDE)
#define GEMM_SMEM_BYTES ((2*ASZ + 2*BSZ)*4)

__global__ void __launch_bounds__(256)
tcgemm_q(const float* __restrict__ A, const float* __restrict__ Bm,
         const float* __restrict__ bias, float* __restrict__ C,
         int M, int N, int K)
{
    extern __shared__ float smf[];
    float* As = smf;
    float* Bs = smf + 2*ASZ;

    int tid  = threadIdx.x;
    int warp = tid >> 5, lane = tid & 31;
    int g = lane >> 2, t = lane & 3;
    int wm = warp >> 2, wn = warp & 3;
    int bm = blockIdx.y * 128, bn = blockIdx.x * 128;

    int arow = tid >> 3, ac4 = (tid & 7) << 2;
    int bkk  = tid >> 5, bn4 = (tid & 31) << 2;

    float acc[4][4][4];
    #pragma unroll
    for (int mi = 0; mi < 4; mi++)
        #pragma unroll
        for (int ni = 0; ni < 4; ni++)
            #pragma unroll
            for (int r = 0; r < 4; r++) acc[mi][ni][r] = 0.f;

#define QSTAGE(K0, BUF) do {                                                     \
        unsigned sa = (unsigned)__cvta_generic_to_shared(As + (BUF)*ASZ);        \
        unsigned sb = (unsigned)__cvta_generic_to_shared(Bs + (BUF)*BSZ);        \
        _Pragma("unroll")                                                        \
        for (int i = 0; i < 4; i++) {                                            \
            int row = arow + i*32;                                               \
            unsigned dst = sa + (unsigned)(row*ASTRIDE + ac4)*4u;                \
            const float* src = A + (size_t)(bm+row)*K + (K0) + ac4;              \
            asm volatile("cp.async.cg.shared.global [%0], [%1], 16;"             \
                         :: "r"(dst), "l"(src));                                 \
        }                                                                        \
        _Pragma("unroll")                                                        \
        for (int i = 0; i < 4; i++) {                                            \
            int kk = bkk + i*8;                                                  \
            unsigned dst = sb + (unsigned)(kk*BSTRIDE + bn4)*4u;                 \
            const float* src = Bm + (size_t)((K0)+kk)*N + bn + bn4;              \
            asm volatile("cp.async.cg.shared.global [%0], [%1], 16;"             \
                         :: "r"(dst), "l"(src));                                 \
        }                                                                        \
        asm volatile("cp.async.commit_group;");                                  \
    } while (0)

#define QCOMPUTE(BUF) do {                                                       \
        const float* Ab = As + (BUF)*ASZ;                                        \
        const float* Bb = Bs + (BUF)*BSZ;                                        \
        _Pragma("unroll")                                                        \
        for (int ks = 0; ks < 4; ks++) {                                         \
            int kb = ks*8;                                                       \
            unsigned ah[4][4], al[4][4];                                         \
            _Pragma("unroll")                                                    \
            for (int mi = 0; mi < 4; mi++) {                                     \
                int mrow = wm*64 + mi*16;                                        \
                float v0 = Ab[(mrow +     g)*ASTRIDE + kb + t    ];              \
                float v1 = Ab[(mrow + 8 + g)*ASTRIDE + kb + t    ];              \
                float v2 = Ab[(mrow +     g)*ASTRIDE + kb + t + 4];              \
                float v3 = Ab[(mrow + 8 + g)*ASTRIDE + kb + t + 4];              \
                ah[mi][0] = f2tf(v0); ah[mi][1] = f2tf(v1);                      \
                ah[mi][2] = f2tf(v2); ah[mi][3] = f2tf(v3);                      \
                al[mi][0] = f2tf(v0 - __uint_as_float(ah[mi][0]));               \
                al[mi][1] = f2tf(v1 - __uint_as_float(ah[mi][1]));               \
                al[mi][2] = f2tf(v2 - __uint_as_float(ah[mi][2]));               \
                al[mi][3] = f2tf(v3 - __uint_as_float(ah[mi][3]));               \
            }                                                                    \
            unsigned bh[4][2], bl[4][2];                                         \
            _Pragma("unroll")                                                    \
            for (int ni = 0; ni < 4; ni++) {                                     \
                int nc = wn*32 + ni*8;                                           \
                float u0 = Bb[(kb + t    )*BSTRIDE + nc + g];                    \
                float u1 = Bb[(kb + t + 4)*BSTRIDE + nc + g];                    \
                bh[ni][0] = f2tf(u0); bh[ni][1] = f2tf(u1);                      \
                bl[ni][0] = f2tf(u0 - __uint_as_float(bh[ni][0]));               \
                bl[ni][1] = f2tf(u1 - __uint_as_float(bh[ni][1]));               \
            }                                                                    \
            _Pragma("unroll")                                                    \
            for (int mi = 0; mi < 4; mi++)                                       \
                _Pragma("unroll")                                                \
                for (int ni = 0; ni < 4; ni++) {                                 \
                    mma8(acc[mi][ni], al[mi], bh[ni]);                           \
                    mma8(acc[mi][ni], ah[mi], bl[ni]);                           \
                    mma8(acc[mi][ni], ah[mi], bh[ni]);                           \
                }                                                                \
        }                                                                        \
    } while (0)

    int nch = K >> 5;
    QSTAGE(0, 0);
    int buf = 0;
    for (int c = 1; c < nch; c++) {
        QSTAGE(c*32, buf^1);
        asm volatile("cp.async.wait_group 1;");
        __syncthreads();
        QCOMPUTE(buf);
        __syncthreads();
        buf ^= 1;
    }
    asm volatile("cp.async.wait_group 0;");
    __syncthreads();
    QCOMPUTE(buf);

    #pragma unroll
    for (int mi = 0; mi < 4; mi++) {
        #pragma unroll
        for (int half = 0; half < 2; half++) {
            int m = bm + wm*64 + mi*16 + half*8 + g;
            #pragma unroll
            for (int ni = 0; ni < 4; ni++) {
                int n = bn + wn*32 + ni*8 + t*2;
                C[(size_t)m*N + n]     = acc[mi][ni][half*2+0] + bias[n];
                C[(size_t)m*N + n + 1] = acc[mi][ni][half*2+1] + bias[n+1];
            }
        }
    }
#undef QSTAGE
#undef QCOMPUTE
}

// ---------------- bf16 tensor-core GEMM 128x128x32, 2-stage, ldmatrix frags ---
#define BH  40            // halves per smem row (32 data + 8 pad); 80B row stride
#define TILEH (128*BH)
#define BF_SMEM_BYTES (2*2*TILEH*2)

template<int EPI, int OUTBF>
__global__ void __launch_bounds__(256)
bfgemm(const __nv_bfloat16* __restrict__ A, const __nv_bfloat16* __restrict__ Bt,
       const float* __restrict__ bias, void* __restrict__ Cout,
       int M, int N, int K, const float* __restrict__ res)
{
    extern __shared__ __nv_bfloat16 smh[];
    __nv_bfloat16* sA = smh;                 // 2 * TILEH
    __nv_bfloat16* sB = smh + 2*TILEH;       // 2 * TILEH

    int tid  = threadIdx.x;
    int warp = tid >> 5, lane = tid & 31;
    int g = lane >> 2, t = lane & 3;
    int wm = warp >> 2, wn = warp & 3;
    int bm = blockIdx.y * 128, bn = blockIdx.x * 128;

    int tA = lane >> 3;
    int arow_f = ((tA & 1) << 3) + (lane & 7);
    int akofs  = (tA >> 1) << 3;
    int brow_f = lane & 7;
    int bkofs  = ((lane >> 3) & 1) << 3;

    float acc[4][4][4];
    #pragma unroll
    for (int mi = 0; mi < 4; mi++)
        #pragma unroll
        for (int ni = 0; ni < 4; ni++)
            #pragma unroll
            for (int r = 0; r < 4; r++) acc[mi][ni][r] = 0.f;

#define BSTAGE(K0, BUF) do {                                                     \
        unsigned sa = (unsigned)__cvta_generic_to_shared(sA + (BUF)*TILEH);      \
        unsigned sb = (unsigned)__cvta_generic_to_shared(sB + (BUF)*TILEH);      \
        _Pragma("unroll")                                                        \
        for (int i = 0; i < 2; i++) {                                            \
            int p = tid + i*256;                                                 \
            int row = p >> 2, c8 = (p & 3) << 3;                                 \
            unsigned dsta = sa + (unsigned)(row*BH + c8)*2u;                     \
            const __nv_bfloat16* srca = A + (size_t)(bm+row)*K + (K0) + c8;      \
            asm volatile("cp.async.cg.shared.global [%0], [%1], 16;"             \
                         :: "r"(dsta), "l"(srca));                               \
            unsigned dstb = sb + (unsigned)(row*BH + c8)*2u;                     \
            const __nv_bfloat16* srcb = Bt + (size_t)(bn+row)*K + (K0) + c8;     \
            asm volatile("cp.async.cg.shared.global [%0], [%1], 16;"             \
                         :: "r"(dstb), "l"(srcb));                               \
        }                                                                        \
        asm volatile("cp.async.commit_group;");                                  \
    } while (0)

#define BCOMPUTE(BUF) do {                                                       \
        unsigned sa = (unsigned)__cvta_generic_to_shared(sA + (BUF)*TILEH);      \
        unsigned sb = (unsigned)__cvta_generic_to_shared(sB + (BUF)*TILEH);      \
        _Pragma("unroll")                                                        \
        for (int ks = 0; ks < 2; ks++) {                                         \
            unsigned a[4][4], b[4][2];                                           \
            _Pragma("unroll")                                                    \
            for (int mi = 0; mi < 4; mi++) {                                     \
                unsigned ad = sa + (unsigned)((wm*64 + mi*16 + arow_f)*BH        \
                                              + ks*16 + akofs)*2u;               \
                ldmx4(a[mi], ad);                                                \
            }                                                                    \
            _Pragma("unroll")                                                    \
            for (int ni = 0; ni < 4; ni++) {                                     \
                unsigned bd = sb + (unsigned)((wn*32 + ni*8 + brow_f)*BH         \
                                              + ks*16 + bkofs)*2u;               \
                ldmx2(b[ni], bd);                                                \
            }                                                                    \
            _Pragma("unroll")                                                    \
            for (int mi = 0; mi < 4; mi++)                                       \
                _Pragma("unroll")                                                \
                for (int ni = 0; ni < 4; ni++)                                   \
                    mma16(acc[mi][ni], a[mi], b[ni]);                            \
        }                                                                        \
    } while (0)

    int nch = K >> 5;
    BSTAGE(0, 0);
    int buf = 0;
    for (int c = 1; c < nch; c++) {
        BSTAGE(c*32, buf^1);
        asm volatile("cp.async.wait_group 1;");
        __syncthreads();
        BCOMPUTE(buf);
        __syncthreads();
        buf ^= 1;
    }
    asm volatile("cp.async.wait_group 0;");
    __syncthreads();
    BCOMPUTE(buf);

    // epilogue
    #pragma unroll
    for (int mi = 0; mi < 4; mi++) {
        #pragma unroll
        for (int half = 0; half < 2; half++) {
            int m = bm + wm*64 + mi*16 + half*8 + g;
            int outrow = m;
            if (EPI == 3) {
                int bw = m / Ntok, nt = m % Ntok;
                int bimg = bw >> 6, rem = bw & 63;
                int wh = rem >> 3, ww = rem & 7;
                int hr = wh*WS + nt/WS;
                int wc = ww*WS + nt%WS;
                outrow = bimg*(Himg*Wimg) + hr*Wimg + wc;
            }
            #pragma unroll
            for (int ni = 0; ni < 4; ni++) {
                int n = bn + wn*32 + ni*8 + t*2;
                float v0 = acc[mi][ni][half*2+0] + bias[n];
                float v1 = acc[mi][ni][half*2+1] + bias[n+1];
                if (EPI == 1) { v0 = gelu_f(v0); v1 = gelu_f(v1); }
                if (EPI == 2) { v0 += res[(size_t)m*N + n]; v1 += res[(size_t)m*N + n + 1]; }
                if (EPI == 3) { v0 += res[(size_t)outrow*N + n]; v1 += res[(size_t)outrow*N + n + 1]; }
                if (OUTBF) {
                    __nv_bfloat162 p; p.x = __float2bfloat16(v0); p.y = __float2bfloat16(v1);
                    *(__nv_bfloat162*)((__nv_bfloat16*)Cout + (size_t)outrow*N + n) = p;
                } else {
                    float* Cf = (float*)Cout;
                    Cf[(size_t)outrow*N + n]     = v0;
                    Cf[(size_t)outrow*N + n + 1] = v1;
                }
            }
        }
    }
#undef BSTAGE
#undef BCOMPUTE
}

// ---------------- fused top-k + gathers (one block per head-window) -----------
// Computes channel & spatial selections from the q tile in smem, then emits
// g_qc (gathered channels, bf16), g_vin (gathered tokens, bf16), g_sidx.
__global__ void topk_gather_kernel(const float* __restrict__ wch, const float* __restrict__ bch)
{
    int bn = blockIdx.x;
    int bw = bn >> 3, hh = bn & 7;
    int tid = threadIdx.x;  // 64 threads
    __shared__ float sh[Ntok*33];
    __shared__ float feat[2*HDd];
    __shared__ float sp[HDd];
    __shared__ float tm[Ntok];
    __shared__ int   selflag[Ntok];
    __shared__ int   scid[KCH];
    __shared__ int   ssid[KSPT];

    for (int e = tid; e < Ntok*HDd; e += 64) {
        int n = e >> 5, d = e & 31;
        sh[n*33 + d] = g_q[((size_t)bw*Ntok + n)*Cdim + hh*HDd + d];
    }
    __syncthreads();

    if (tid < HDd) {
        float m = 0.f, mx = -1e30f;
        #pragma unroll 7
        for (int n = 0; n < Ntok; n++) {
            float v = sh[n*33 + tid];
            m += v; mx = fmaxf(mx, v);
        }
        feat[tid] = m * (1.0f/Ntok);
        feat[HDd + tid] = mx;
    }
    __syncthreads();

    if (tid < HDd) {
        float s = bch[tid];
        #pragma unroll 8
        for (int i = 0; i < 2*HDd; i++) s += feat[i]*wch[i*HDd + tid];
        sp[tid] = gelu_f(s);   // softmax monotone; gelu-rank == softmax-rank
    }
    __syncthreads();

    if (tid < HDd) {
        float v = sp[tid];
        int rank = 0;
        #pragma unroll 8
        for (int i = 0; i < HDd; i++) {
            float u = sp[i];
            rank += (u > v) || (u == v && i < tid);
        }
        bool sel = rank < KCH;
        unsigned mask = __ballot_sync(0xffffffffu, sel);
        if (sel) {
            int pos = __popc(mask & ((1u << tid) - 1));
            scid[pos] = tid;
        }
    }

    // spatial top-k by token sum (monotone vs mean)
    if (tid < Ntok) {
        float m = 0.f;
        #pragma unroll 8
        for (int d = 0; d < HDd; d++) m += sh[tid*33 + d];
        tm[tid] = m;
    }
    __syncthreads();
    if (tid < Ntok) {
        float v = tm[tid];
        int rank = 0;
        for (int i = 0; i < Ntok; i++) {
            float u = tm[i];
            rank += (u > v) || (u == v && i < tid);
        }
        selflag[tid] = (rank < KSPT) ? 1 : 0;
    }
    __syncthreads();
    if (tid < Ntok && selflag[tid]) {
        int pos = 0;
        for (int i = 0; i < tid; i++) pos += selflag[i];
        ssid[pos] = tid;
        g_sidx[bn*KSPT + pos] = tid;
    }
    __syncthreads();

    // gather qc: (49 tokens x 16 selected channels) bf16
    for (int e = tid; e < Ntok*KCH; e += 64) {
        int n = e >> 4, j = e & 15;
        g_qc[((size_t)bw*Ntok + n)*(Cdim/2) + hh*KCH + j] =
            __float2bfloat16(sh[n*33 + scid[j]]);
    }
    // gather vin: (28 selected tokens x 32 dims) bf16
    for (int e = tid; e < KSPT*HDd; e += 64) {
        int t = e >> 5, d = e & 31;
        g_vin[((size_t)bw*KSPT + t)*Cdim + hh*HDd + d] =
            __float2bfloat16(sh[ssid[t]*33 + d]);
    }
}

// ---------------- attention core (one block per window-head) ----------------
__global__ void attn_kernel(const float* __restrict__ rpb_table)
{
    int bw = blockIdx.x >> 3;
    int hh = blockIdx.x & 7;
    int bn = blockIdx.x;
    int tid = threadIdx.x;   // 128 threads

    __shared__ float s_k[Ntok][KCH];
    __shared__ float s_q[KSPT][KCH];
    __shared__ float s_v[KSPT][HDd];
    __shared__ float s_at[Ntok][KSPT];
    __shared__ int   s_si[KSPT];

    if (tid < KSPT) s_si[tid] = g_sidx[bn*KSPT + tid];
    __syncthreads();

    for (int e = tid; e < Ntok*KCH; e += 128) {
        int n = e >> 4, j = e & 15;
        s_k[n][j] = __bfloat162float(g_kb[((size_t)bw*Ntok + n)*(Cdim/2) + hh*KCH + j]);
    }
    for (int e = tid; e < KSPT*KCH; e += 128) {
        int t = e >> 4, j = e & 15;
        s_q[t][j] = __bfloat162float(g_qc[((size_t)bw*Ntok + s_si[t])*(Cdim/2) + hh*KCH + j]) * QK_SCALE;
    }
    for (int e = tid; e < KSPT*HDd; e += 128) {
        int t = e >> 5, d = e & 31;
        s_v[t][d] = __bfloat162float(g_vp[((size_t)bw*KSPT + t)*Cdim + hh*HDd + d]);
    }
    __syncthreads();

    for (int e = tid; e < Ntok*KSPT; e += 128) {
        int n = e / KSPT, t = e % KSPT;
        float s = 0.f;
        #pragma unroll
        for (int j = 0; j < KCH; j++) s += s_k[n][j]*s_q[t][j];
        int m = s_si[t];
        int di0 = n/WS - m/WS + (WS-1);
        int di1 = n%WS - m%WS + (WS-1);
        s += rpb_table[(di0*(2*WS-1) + di1)*NHh + hh];
        s_at[n][t] = s;
    }
    __syncthreads();

    if (tid < Ntok) {
        float mean = 0.f, mx = -1e30f;
        #pragma unroll
        for (int t = 0; t < KSPT; t++) {
            float v = s_at[tid][t];
            mean += v; mx = fmaxf(mx, v);
        }
        mean *= (1.0f/KSPT);
        float gate = 1.0f / (1.0f + expf(-mean));
        float sum = 0.f;
        #pragma unroll
        for (int t = 0; t < KSPT; t++) {
            float e = expf(s_at[tid][t] - mx);
            s_at[tid][t] = e; sum += e;
        }
        float sc = gate / sum;
        #pragma unroll
        for (int t = 0; t < KSPT; t++) s_at[tid][t] *= sc;
    }
    __syncthreads();

    for (int e = tid; e < Ntok*HDd; e += 128) {
        int n = e >> 5, d = e & 31;
        float s = 0.f;
        #pragma unroll
        for (int t = 0; t < KSPT; t++) s += s_at[n][t]*s_v[t][d];
        g_o[((size_t)bw*Ntok + n)*Cdim + hh*HDd + d] = __float2bfloat16(s);
    }
}

// ---------------- launch ----------------
extern "C" void kernel_launch(void* const* d_in, const int* in_sizes, int n_in,
                              void* d_out, int out_size)
{
    const float* x       = (const float*)d_in[0];
    const float* norm1_g = (const float*)d_in[1];
    const float* norm1_b = (const float*)d_in[2];
    const float* wq      = (const float*)d_in[3];
    const float* bq      = (const float*)d_in[4];
    const float* wk      = (const float*)d_in[5];
    const float* bk      = (const float*)d_in[6];
    const float* wv      = (const float*)d_in[7];
    const float* bv      = (const float*)d_in[8];
    const float* wproj   = (const float*)d_in[9];
    const float* bproj   = (const float*)d_in[10];
    const float* wch     = (const float*)d_in[11];
    const float* bch     = (const float*)d_in[12];
    const float* rpb     = (const float*)d_in[13];
    const float* norm2_g = (const float*)d_in[14];
    const float* norm2_b = (const float*)d_in[15];
    const float* w1      = (const float*)d_in[16];
    const float* b1      = (const float*)d_in[17];
    const float* w2      = (const float*)d_in[18];
    const float* b2      = (const float*)d_in[19];
    float* out = (float*)d_out;

    float *xw, *q, *xr;
    __nv_bfloat16 *qc, *kkb, *vin, *vp, *oo, *x2, *hb, *wkb, *wvb, *wpb, *w1b, *w2b;
    cudaGetSymbolAddress((void**)&xw, g_xw);
    cudaGetSymbolAddress((void**)&q,  g_q);
    cudaGetSymbolAddress((void**)&qc, g_qc);
    cudaGetSymbolAddress((void**)&kkb, g_kb);
    cudaGetSymbolAddress((void**)&vin,g_vin);
    cudaGetSymbolAddress((void**)&vp, g_vp);
    cudaGetSymbolAddress((void**)&oo, g_o);
    cudaGetSymbolAddress((void**)&xr, g_xr);
    cudaGetSymbolAddress((void**)&x2, g_x2);
    cudaGetSymbolAddress((void**)&hb, g_hb);
    cudaGetSymbolAddress((void**)&wkb, g_wkb);
    cudaGetSymbolAddress((void**)&wvb, g_wvb);
    cudaGetSymbolAddress((void**)&wpb, g_wpb);
    cudaGetSymbolAddress((void**)&w1b, g_w1b);
    cudaGetSymbolAddress((void**)&w2b, g_w2b);

    static bool attr_done = false;
    if (!attr_done) {
        cudaFuncSetAttribute(tcgemm_q, cudaFuncAttributeMaxDynamicSharedMemorySize, GEMM_SMEM_BYTES);
        cudaFuncSetAttribute(bfgemm<0,0>, cudaFuncAttributeMaxDynamicSharedMemorySize, BF_SMEM_BYTES);
        cudaFuncSetAttribute(bfgemm<0,1>, cudaFuncAttributeMaxDynamicSharedMemorySize, BF_SMEM_BYTES);
        cudaFuncSetAttribute(bfgemm<3,0>, cudaFuncAttributeMaxDynamicSharedMemorySize, BF_SMEM_BYTES);
        cudaFuncSetAttribute(bfgemm<1,1>, cudaFuncAttributeMaxDynamicSharedMemorySize, BF_SMEM_BYTES);
        cudaFuncSetAttribute(bfgemm<2,0>, cudaFuncAttributeMaxDynamicSharedMemorySize, BF_SMEM_BYTES);
        attr_done = true;
    }

    // 0. weight transposes -> bf16 [N][K] (single fused launch)
    convw_all<<<(CONV_TOTAL+255)/256, 256>>>(wk, wv, wproj, w1, w2);

    // 1. LN1 + window partition (fp32 out for Q)
    ln_kernel<0><<<Mrows, 256>>>(x, norm1_g, norm1_b, xw);

    // 2. Q = xw @ wq + bq  (3xTF32 — near-fp32, feeds top-k rankings)
    tcgemm_q<<<dim3(Cdim/128, Mrows/128), 256, GEMM_SMEM_BYTES>>>(xw, wq, bq, q, Mrows, Cdim, Cdim);

    // 3. fused channel+spatial top-k + both gathers
    topk_gather_kernel<<<BNh, 64>>>(wch, bch);

    // 4. K = qcha1 @ wk + bk   (bf16 TC, bf16 out)
    bfgemm<0,1><<<dim3((Cdim/2)/128, Mrows/128), 256, BF_SMEM_BYTES>>>(qc, wkb, bk, kkb, Mrows, Cdim/2, Cdim/2, nullptr);

    // 5. V = vin @ wv + bv  (bf16 out)
    bfgemm<0,1><<<dim3(Cdim/128, (BW*KSPT)/128), 256, BF_SMEM_BYTES>>>(vin, wvb, bv, vp, BW*KSPT, Cdim, Cdim, nullptr);

    // 6. attention (bf16 out)
    attn_kernel<<<BNh, 128>>>(rpb);

    // 7. out-proj + window reverse + shortcut  -> xr (fp32)
    bfgemm<3,0><<<dim3(Cdim/128, Mrows/128), 256, BF_SMEM_BYTES>>>(oo, wpb, bproj, xr, Mrows, Cdim, Cdim, x);

    // 8. LN2 (bf16 out)
    ln_kernel<1><<<Mrows, 256>>>(xr, norm2_g, norm2_b, x2);

    // 9. h = gelu(x2 @ w1 + b1)  (bf16 out)
    bfgemm<1,1><<<dim3(MLPH/128, Mrows/128), 256, BF_SMEM_BYTES>>>(x2, w1b, b1, hb, Mrows, MLPH, Cdim, nullptr);

    // 10. out = xr + h @ w2 + b2  (fp32)
    bfgemm<2,0><<<dim3(Cdim/128, Mrows/128), 256, BF_SMEM_BYTES>>>(hb, w2b, b2, out, Mrows, Cdim, MLPH, xr);
}